// round 9
// baseline (speedup 1.0000x reference)
#include <cuda_runtime.h>
#include <cuda_bf16.h>
#include <math.h>
#include <stdint.h>

#define BB 2
#define CC 512
#define SS 8192
#define NHW 1024
#define SQRT_C     22.627416997969522f
#define INV_SQRT_C 0.04419417382415922f

// bf16 MK tiles: 128 rows x 64 k bf16, row stride 72 bf16 (144 B, conflict-free)
#define KSLAB 64
#define MKP 72
#define SZ_MK (128 * MKP * 2)    // 18432 B
#define HALF_MK 64               // byte offset of second 32-k half (32 bf16)
// fp8 MK tiles: 128 rows x 128 k fp8, row stride 144 B (conflict-free)
#define K8SLAB 128
#define MK8B 144
#define SZ_MK8 (128 * MK8B)      // 18432 B
#define SMEM_GEMM (3 * 2 * 18432)   // 110592 B, 2 CTAs/SM

// Scratch
__device__ float         g_scale[(size_t)BB * SS];
__device__ __nv_bfloat16 g_hn[(size_t)BB * SS * CC];   // [b][s][c]
__device__ uint8_t       g_q8[(size_t)BB * SS * CC];   // [b][s][c] e4m3
__device__ uint8_t       g_k8[(size_t)BB * SS * CC];   // [b][s][c] e4m3
__device__ uint8_t       g_v8[(size_t)BB * CC * SS];   // [b][c][s] e4m3
__device__ uint8_t       g_p8[(size_t)BB * SS * SS];   // [b][sq][sk] e4m3 exp
__device__ __nv_bfloat16 g_o [(size_t)BB * SS * CC];   // [b][s][c]
__device__ __nv_bfloat16 g_w [4][(size_t)CC * CC];     // bf16 weights [co][ci]
__device__ float         g_rsum[(size_t)BB * SS];

// ---------------------------------------------------------------------------
// PTX helpers
// ---------------------------------------------------------------------------
__device__ __forceinline__ uint32_t smaddr(const void* p) {
    return (uint32_t)__cvta_generic_to_shared(p);
}
__device__ __forceinline__ void cp16(uint32_t d, const void* s) {
    asm volatile("cp.async.cg.shared.global [%0], [%1], 16;\n" :: "r"(d), "l"(s));
}
__device__ __forceinline__ void cp_commit() { asm volatile("cp.async.commit_group;\n"); }
template<int N> __device__ __forceinline__ void cp_wait() {
    asm volatile("cp.async.wait_group %0;\n" :: "n"(N));
}
__device__ __forceinline__ void ldsm4(uint32_t* r, uint32_t a) {
    asm volatile("ldmatrix.sync.aligned.m8n8.x4.shared.b16 {%0,%1,%2,%3}, [%4];"
                 : "=r"(r[0]), "=r"(r[1]), "=r"(r[2]), "=r"(r[3]) : "r"(a));
}
__device__ __forceinline__ void mma16816(float* c, const uint32_t* a, const uint32_t* b) {
    asm volatile("mma.sync.aligned.m16n8k16.row.col.f32.bf16.bf16.f32 "
                 "{%0,%1,%2,%3},{%4,%5,%6,%7},{%8,%9},{%0,%1,%2,%3};"
                 : "+f"(c[0]), "+f"(c[1]), "+f"(c[2]), "+f"(c[3])
                 : "r"(a[0]), "r"(a[1]), "r"(a[2]), "r"(a[3]), "r"(b[0]), "r"(b[1]));
}
__device__ __forceinline__ void mma16832f8(float* c, const uint32_t* a, const uint32_t* b) {
    asm volatile("mma.sync.aligned.m16n8k32.row.col.f32.e4m3.e4m3.f32 "
                 "{%0,%1,%2,%3},{%4,%5,%6,%7},{%8,%9},{%0,%1,%2,%3};"
                 : "+f"(c[0]), "+f"(c[1]), "+f"(c[2]), "+f"(c[3])
                 : "r"(a[0]), "r"(a[1]), "r"(a[2]), "r"(a[3]), "r"(b[0]), "r"(b[1]));
}
__device__ __forceinline__ uint16_t pack_e4m3(float hi, float lo) {
    uint16_t r;
    asm("cvt.rn.satfinite.e4m3x2.f32 %0, %1, %2;" : "=h"(r) : "f"(hi), "f"(lo));
    return r;
}
__device__ __forceinline__ uint32_t e4m3x2_to_h2(uint16_t v) {
    uint32_t r;
    asm("cvt.rn.f16x2.e4m3x2 %0, %1;" : "=r"(r) : "h"(v));
    return r;
}

// ---------------------------------------------------------------------------
// stagers (128 threads)
// ---------------------------------------------------------------------------
__device__ __forceinline__ void stageMK(uint32_t dst, const __nv_bfloat16* g,
                                        int ld, int r0, int k0, int tid) {
#pragma unroll
    for (int j = 0; j < 8; j++) {
        int c = j * 128 + tid;
        int row = c >> 3, off = (c & 7) << 3;
        cp16(dst + (uint32_t)(row * MKP + off) * 2, g + (size_t)(r0 + row) * ld + k0 + off);
    }
}
__device__ __forceinline__ void stage8(uint32_t dst, const uint8_t* g,
                                       int ld, int r0, int k0, int tid) {
#pragma unroll
    for (int j = 0; j < 8; j++) {
        int c = j * 128 + tid;
        int row = c >> 3, off = (c & 7) << 4;
        cp16(dst + (uint32_t)(row * MK8B + off), g + (size_t)(r0 + row) * ld + k0 + off);
    }
}

// ---------------------------------------------------------------------------
// fragment loaders (warp tile 64x64), all non-transposed LDSM
// ---------------------------------------------------------------------------
__device__ __forceinline__ void fragA_MK(uint32_t a[4][4], uint32_t base,
                                         int wm, int lane, int ks) {
    int g = lane >> 3;
#pragma unroll
    for (int mt = 0; mt < 4; mt++) {
        int row = wm + mt * 16 + ((g & 1) << 3) + (lane & 7);
        int col = ks * 16 + ((g >> 1) << 3);
        ldsm4(a[mt], base + (uint32_t)(row * MKP + col) * 2);
    }
}
__device__ __forceinline__ void fragB_MK(uint32_t b[8][4], uint32_t base, int wn, int lane) {
    int g = lane >> 3;
#pragma unroll
    for (int nt = 0; nt < 8; nt++) {
        int row = wn + nt * 8 + (lane & 7);
        int col = g << 3;
        ldsm4(b[nt], base + (uint32_t)(row * MKP + col) * 2);
    }
}
// fp8: byte-addressed, kb = byte offset of 32-fp8 group (A) / 64-fp8 group (B)
__device__ __forceinline__ void fragA8(uint32_t a[4][4], uint32_t base,
                                       int wm, int lane, int kb) {
    int g = lane >> 3;
#pragma unroll
    for (int mt = 0; mt < 4; mt++) {
        int row = wm + mt * 16 + ((g & 1) << 3) + (lane & 7);
        int cb = kb + ((g >> 1) << 4);
        ldsm4(a[mt], base + (uint32_t)(row * MK8B) + cb);
    }
}
__device__ __forceinline__ void fragB8(uint32_t b[8][4], uint32_t base,
                                       int wn, int lane, int kb) {
    int g = lane >> 3;
#pragma unroll
    for (int nt = 0; nt < 8; nt++) {
        int row = wn + nt * 8 + (lane & 7);
        int cb = kb + (g << 4);
        ldsm4(b[nt], base + (uint32_t)(row * MK8B) + cb);
    }
}

#define GEMM_VARS                                                     \
    extern __shared__ __align__(16) char dynsm[];                     \
    uint32_t sbase = smaddr(dynsm);                                   \
    int tid = threadIdx.x, lane = tid & 31, wid = tid >> 5;           \
    int wm = (wid >> 1) * 64, wn = (wid & 1) * 64;                    \
    int qr = lane >> 2, qc = lane & 3;                                \
    float acc[4][8][4];                                               \
    _Pragma("unroll") for (int mt = 0; mt < 4; mt++)                  \
    _Pragma("unroll") for (int nt = 0; nt < 8; nt++)                  \
    _Pragma("unroll") for (int i = 0; i < 4; i++) acc[mt][nt][i] = 0.f;

// bf16 32-k half-slab
#define SLAB_BF(baseA, baseB)                                         \
    {                                                                 \
        uint32_t bfr[8][4];                                           \
        fragB_MK(bfr, (baseB), wn, lane);                             \
        _Pragma("unroll")                                             \
        for (int ks = 0; ks < 2; ks++) {                              \
            uint32_t afr[4][4];                                       \
            fragA_MK(afr, (baseA), wm, lane, ks);                     \
            _Pragma("unroll") for (int mt = 0; mt < 4; mt++)          \
            _Pragma("unroll") for (int nt = 0; nt < 8; nt++)          \
                mma16816(acc[mt][nt], afr[mt], &bfr[nt][ks * 2]);     \
        }                                                             \
    }
#define SLAB64_BF(baseA, baseB)                                       \
    SLAB_BF((baseA), (baseB));                                        \
    SLAB_BF((baseA) + HALF_MK, (baseB) + HALF_MK);

// fp8 128-k slab = two 64-fp8 groups
#define SLAB128_F8(baseA, baseB)                                      \
    _Pragma("unroll")                                                 \
    for (int kb0 = 0; kb0 < 128; kb0 += 64) {                         \
        uint32_t bfr[8][4];                                           \
        fragB8(bfr, (baseB), wn, lane, kb0);                          \
        _Pragma("unroll")                                             \
        for (int ks = 0; ks < 2; ks++) {                              \
            uint32_t afr[4][4];                                       \
            fragA8(afr, (baseA), wm, lane, kb0 + 32 * ks);            \
            _Pragma("unroll") for (int mt = 0; mt < 4; mt++)          \
            _Pragma("unroll") for (int nt = 0; nt < 8; nt++)          \
                mma16832f8(acc[mt][nt], afr[mt], &bfr[nt][ks * 2]);   \
        }                                                             \
    }

#define ROT3(s0, s1, s2) { uint32_t _t = s0; s0 = s1; s1 = s2; s2 = _t; }

// ---------------------------------------------------------------------------
// prep: fp32 weights -> bf16
// ---------------------------------------------------------------------------
__global__ void prep_w_kernel(const float* __restrict__ wq, const float* __restrict__ wk,
                              const float* __restrict__ wv, const float* __restrict__ wo) {
    int which = blockIdx.y;
    const float* w = which == 0 ? wq : which == 1 ? wk : which == 2 ? wv : wo;
    int i = blockIdx.x * 256 + threadIdx.x;
    g_w[which][i] = __float2bfloat16_rn(w[i]);
}

// ---------------------------------------------------------------------------
// per-token rms scale
// ---------------------------------------------------------------------------
__global__ void norm_kernel(const float* __restrict__ x) {
    int s = blockIdx.x * 256 + threadIdx.x;
    int b = blockIdx.y;
    const float* xb = x + (size_t)b * CC * SS + s;
    float ss = 0.f;
#pragma unroll 8
    for (int c = 0; c < CC; c++) {
        float v = xb[(size_t)c * SS];
        ss += v * v;
    }
    g_scale[b * SS + s] = SQRT_C / fmaxf(sqrtf(ss), 1e-12f);
}

// ---------------------------------------------------------------------------
// transpose x[c][s] -> hn[s][c] bf16, applying scale[s]*gamma[c]
// ---------------------------------------------------------------------------
__global__ void transpose_kernel(const float* __restrict__ x,
                                 const float* __restrict__ gamma) {
    __shared__ float t[32][33];
    int b = blockIdx.z;
    int c0 = blockIdx.x * 32, s0 = blockIdx.y * 32;
    int sx = threadIdx.x & 31, cy = threadIdx.x >> 5;   // 32 x 8
    const float* xb = x + ((size_t)b * CC + c0) * SS + s0;
#pragma unroll
    for (int j = 0; j < 4; j++)
        t[cy + 8 * j][sx] = xb[(size_t)(cy + 8 * j) * SS + sx];
    __syncthreads();
    float gm = gamma[c0 + sx];
#pragma unroll
    for (int j = 0; j < 4; j++) {
        int sr = cy + 8 * j;
        float sc = g_scale[b * SS + s0 + sr];
        g_hn[((size_t)b * SS + s0 + sr) * CC + c0 + sx] =
            __float2bfloat16_rn(t[sx][sr] * sc * gm);
    }
}

// ---------------------------------------------------------------------------
// q/k projection: D[s][co] = hn[s][:] . W[co][:] + bq  -> fp8 [s][c]
// ---------------------------------------------------------------------------
__global__ void __launch_bounds__(128) proj_qk_kernel(
    const float* __restrict__ bq, const float* __restrict__ bk) {

    int z = blockIdx.z, b = z >> 1, which = z & 1;
    const __nv_bfloat16* HN = g_hn + (size_t)b * SS * CC;
    const __nv_bfloat16* W  = g_w[which];
    const float* bias = which ? bk : bq;
    uint8_t* Qout = (which ? g_k8 : g_q8) + (size_t)b * SS * CC;

    int m0 = blockIdx.x * 128;   // s
    int n0 = blockIdx.y * 128;   // co
    GEMM_VARS
    uint32_t a0 = sbase, a1 = a0 + SZ_MK, a2 = a1 + SZ_MK;
    uint32_t b0 = sbase + 3 * SZ_MK, b1 = b0 + SZ_MK, b2 = b1 + SZ_MK;

    stageMK(a0, HN, CC, m0, 0, tid);     stageMK(b0, W, CC, n0, 0, tid);     cp_commit();
    stageMK(a1, HN, CC, m0, KSLAB, tid); stageMK(b1, W, CC, n0, KSLAB, tid); cp_commit();

    const int nIt = CC / KSLAB;   // 8
#pragma unroll
    for (int i = 0; i < nIt; i++) {
        cp_wait<1>();
        __syncthreads();
        SLAB64_BF(a0, b0);
        if (i + 2 < nIt) {
            stageMK(a2, HN, CC, m0, (i + 2) * KSLAB, tid);
            stageMK(b2, W, CC, n0, (i + 2) * KSLAB, tid);
            cp_commit();
        }
        ROT3(a0, a1, a2); ROT3(b0, b1, b2);
    }

#pragma unroll
    for (int mt = 0; mt < 4; mt++) {
        int m = m0 + wm + mt * 16 + qr;
#pragma unroll
        for (int nt = 0; nt < 8; nt++) {
            int n = n0 + wn + nt * 8 + qc * 2;
            float bi0 = bias[n], bi1 = bias[n + 1];
            *(uint16_t*)&Qout[(size_t)m * CC + n] =
                pack_e4m3(acc[mt][nt][1] + bi1, acc[mt][nt][0] + bi0);
            *(uint16_t*)&Qout[(size_t)(m + 8) * CC + n] =
                pack_e4m3(acc[mt][nt][3] + bi1, acc[mt][nt][2] + bi0);
        }
    }
}

// ---------------------------------------------------------------------------
// v projection: D[co][s] = W[co][:] . hn[s][:] + bv  -> fp8 [c][s]
// ---------------------------------------------------------------------------
__global__ void __launch_bounds__(128) proj_v_kernel(const float* __restrict__ bv) {
    int b = blockIdx.z;
    int m0 = blockIdx.y * 128;   // co
    int n0 = blockIdx.x * 128;   // s
    const __nv_bfloat16* W  = g_w[2];
    const __nv_bfloat16* HN = g_hn + (size_t)b * SS * CC;
    uint8_t* Vout = g_v8 + (size_t)b * CC * SS;
    GEMM_VARS
    uint32_t a0 = sbase, a1 = a0 + SZ_MK, a2 = a1 + SZ_MK;
    uint32_t b0 = sbase + 3 * SZ_MK, b1 = b0 + SZ_MK, b2 = b1 + SZ_MK;

    stageMK(a0, W, CC, m0, 0, tid);     stageMK(b0, HN, CC, n0, 0, tid);     cp_commit();
    stageMK(a1, W, CC, m0, KSLAB, tid); stageMK(b1, HN, CC, n0, KSLAB, tid); cp_commit();

    const int nIt = CC / KSLAB;
#pragma unroll
    for (int i = 0; i < nIt; i++) {
        cp_wait<1>();
        __syncthreads();
        SLAB64_BF(a0, b0);
        if (i + 2 < nIt) {
            stageMK(a2, W, CC, m0, (i + 2) * KSLAB, tid);
            stageMK(b2, HN, CC, n0, (i + 2) * KSLAB, tid);
            cp_commit();
        }
        ROT3(a0, a1, a2); ROT3(b0, b1, b2);
    }

#pragma unroll
    for (int mt = 0; mt < 4; mt++) {
        int m = m0 + wm + mt * 16 + qr;
        float bi0 = bv[m], bi1 = bv[m + 8];
#pragma unroll
        for (int nt = 0; nt < 8; nt++) {
            int n = n0 + wn + nt * 8 + qc * 2;
            *(uint16_t*)&Vout[(size_t)m * SS + n] =
                pack_e4m3(acc[mt][nt][1] + bi0, acc[mt][nt][0] + bi0);
            *(uint16_t*)&Vout[(size_t)(m + 8) * SS + n] =
                pack_e4m3(acc[mt][nt][3] + bi1, acc[mt][nt][2] + bi1);
        }
    }
}

// ---------------------------------------------------------------------------
// QK^T fp8, compacted grid over allowed tiles; writes exp(scores) fp8
// ---------------------------------------------------------------------------
__global__ void __launch_bounds__(128) qk_kernel() {
    int b = blockIdx.z;
    int bi = blockIdx.x;
    int f = 0;
    while (bi >= 64 * (f + 1)) { bi -= 64 * (f + 1); f++; }
    int r  = bi / (8 * (f + 1));
    int nc = bi % (8 * (f + 1));
    int m0 = (f * 8 + r) * 128;   // sq
    int n0 = nc * 128;            // sk

    const uint8_t* Q = g_q8 + (size_t)b * SS * CC;
    const uint8_t* K = g_k8 + (size_t)b * SS * CC;
    GEMM_VARS
    uint32_t a0 = sbase, a1 = a0 + SZ_MK8, a2 = a1 + SZ_MK8;
    uint32_t b0 = sbase + 3 * SZ_MK8, b1 = b0 + SZ_MK8, b2 = b1 + SZ_MK8;

    stage8(a0, Q, CC, m0, 0, tid);      stage8(b0, K, CC, n0, 0, tid);      cp_commit();
    stage8(a1, Q, CC, m0, K8SLAB, tid); stage8(b1, K, CC, n0, K8SLAB, tid); cp_commit();

    const int nIt = CC / K8SLAB;   // 4
#pragma unroll
    for (int i = 0; i < nIt; i++) {
        cp_wait<1>();
        __syncthreads();
        SLAB128_F8(a0, b0);
        if (i + 2 < nIt) {
            stage8(a2, Q, CC, m0, (i + 2) * K8SLAB, tid);
            stage8(b2, K, CC, n0, (i + 2) * K8SLAB, tid);
            cp_commit();
        }
        ROT3(a0, a1, a2); ROT3(b0, b1, b2);
    }

    uint8_t* P = g_p8 + (size_t)b * SS * SS;
#pragma unroll
    for (int mt = 0; mt < 4; mt++) {
        int m = m0 + wm + mt * 16 + qr;
#pragma unroll
        for (int nt = 0; nt < 8; nt++) {
            int n = n0 + wn + nt * 8 + qc * 2;
            *(uint16_t*)&P[(size_t)m * SS + n] =
                pack_e4m3(__expf(acc[mt][nt][1] * INV_SQRT_C),
                          __expf(acc[mt][nt][0] * INV_SQRT_C));
            *(uint16_t*)&P[(size_t)(m + 8) * SS + n] =
                pack_e4m3(__expf(acc[mt][nt][3] * INV_SQRT_C),
                          __expf(acc[mt][nt][2] * INV_SQRT_C));
        }
    }
}

// ---------------------------------------------------------------------------
// row sums of exp(scores) (fp8 input)
// ---------------------------------------------------------------------------
__global__ void __launch_bounds__(256) rsum_kernel() {
    int sq = blockIdx.x;
    int b  = blockIdx.y;
    const uint32_t* row4 = (const uint32_t*)(g_p8 + ((size_t)b * SS + sq) * SS);
    int L = (sq / NHW + 1) * NHW;
    int n4 = L >> 10;                       // u32 loads per thread (1..8)
    int tid = threadIdx.x, lane = tid & 31, wid = tid >> 5;

    __shared__ float red[8];
    float s = 0.f;
#pragma unroll
    for (int i = 0; i < 8; i++)
        if (i < n4) {
            uint32_t v = row4[i * 256 + tid];
            uint32_t h0 = e4m3x2_to_h2((uint16_t)(v & 0xffffu));
            uint32_t h1 = e4m3x2_to_h2((uint16_t)(v >> 16));
            float2 f0 = __half22float2(*(__half2*)&h0);
            float2 f1 = __half22float2(*(__half2*)&h1);
            s += (f0.x + f0.y) + (f1.x + f1.y);
        }
#pragma unroll
    for (int o = 16; o > 0; o >>= 1) s += __shfl_xor_sync(0xffffffffu, s, o);
    if (lane == 0) red[wid] = s;
    __syncthreads();
    if (tid == 0) {
        float S = 0.f;
#pragma unroll
        for (int i = 0; i < 8; i++) S += red[i];
        g_rsum[b * SS + sq] = S;
    }
}

// ---------------------------------------------------------------------------
// PV fp8: D[sq][c] = (P[sq][:L] . v[c][:L]) / rsum[sq]  -> bf16 [s][c]
// ---------------------------------------------------------------------------
__global__ void __launch_bounds__(128) pv_kernel() {
    int b  = blockIdx.z;
    int m0 = blockIdx.y * 128;   // sq
    int n0 = blockIdx.x * 128;   // c
    int L  = (m0 / NHW + 1) * NHW;
    const int nIt = L / K8SLAB;

    const uint8_t* P = g_p8 + (size_t)b * SS * SS;
    const uint8_t* V = g_v8 + (size_t)b * CC * SS;
    GEMM_VARS
    uint32_t a0 = sbase, a1 = a0 + SZ_MK8, a2 = a1 + SZ_MK8;
    uint32_t b0 = sbase + 3 * SZ_MK8, b1 = b0 + SZ_MK8, b2 = b1 + SZ_MK8;

    stage8(a0, P, SS, m0, 0, tid);      stage8(b0, V, SS, n0, 0, tid);      cp_commit();
    stage8(a1, P, SS, m0, K8SLAB, tid); stage8(b1, V, SS, n0, K8SLAB, tid); cp_commit();

    for (int i = 0; i < nIt; i++) {
        cp_wait<1>();
        __syncthreads();
        SLAB128_F8(a0, b0);
        if (i + 2 < nIt) {
            stage8(a2, P, SS, m0, (i + 2) * K8SLAB, tid);
            stage8(b2, V, SS, n0, (i + 2) * K8SLAB, tid);
            cp_commit();
        }
        ROT3(a0, a1, a2); ROT3(b0, b1, b2);
    }

    __nv_bfloat16* O = g_o + (size_t)b * SS * CC;
#pragma unroll
    for (int mt = 0; mt < 4; mt++) {
        int m = m0 + wm + mt * 16 + qr;
        float inv0 = 1.f / g_rsum[b * SS + m];
        float inv1 = 1.f / g_rsum[b * SS + m + 8];
#pragma unroll
        for (int nt = 0; nt < 8; nt++) {
            int n = n0 + wn + nt * 8 + qc * 2;
            *(__nv_bfloat162*)&O[(size_t)m * CC + n] =
                __floats2bfloat162_rn(acc[mt][nt][0] * inv0, acc[mt][nt][1] * inv0);
            *(__nv_bfloat162*)&O[(size_t)(m + 8) * CC + n] =
                __floats2bfloat162_rn(acc[mt][nt][2] * inv1, acc[mt][nt][3] * inv1);
        }
    }
}

// ---------------------------------------------------------------------------
// O-proj + residual (fp32 out): A = wo (MK), B = g_o (MK rows s), bf16
// ---------------------------------------------------------------------------
__global__ void __launch_bounds__(128) oproj_kernel(
    const float* __restrict__ bo, const float* __restrict__ x,
    float* __restrict__ out) {

    int b  = blockIdx.z;
    int m0 = blockIdx.y * 128;   // c_out
    int n0 = blockIdx.x * 128;   // s

    const __nv_bfloat16* W = g_w[3];
    const __nv_bfloat16* O = g_o + (size_t)b * SS * CC;
    GEMM_VARS
    uint32_t a0 = sbase, a1 = a0 + SZ_MK, a2 = a1 + SZ_MK;
    uint32_t b0 = sbase + 3 * SZ_MK, b1 = b0 + SZ_MK, b2 = b1 + SZ_MK;

    stageMK(a0, W, CC, m0, 0, tid);     stageMK(b0, O, CC, n0, 0, tid);     cp_commit();
    stageMK(a1, W, CC, m0, KSLAB, tid); stageMK(b1, O, CC, n0, KSLAB, tid); cp_commit();

    const int nIt = CC / KSLAB;   // 8
#pragma unroll
    for (int i = 0; i < nIt; i++) {
        cp_wait<1>();
        __syncthreads();
        SLAB64_BF(a0, b0);
        if (i + 2 < nIt) {
            stageMK(a2, W, CC, m0, (i + 2) * KSLAB, tid);
            stageMK(b2, O, CC, n0, (i + 2) * KSLAB, tid);
            cp_commit();
        }
        ROT3(a0, a1, a2); ROT3(b0, b1, b2);
    }

#pragma unroll
    for (int mt = 0; mt < 4; mt++) {
        int m = m0 + wm + mt * 16 + qr;
        float bi0 = bo[m], bi1 = bo[m + 8];
#pragma unroll
        for (int nt = 0; nt < 8; nt++) {
            int n = n0 + wn + nt * 8 + qc * 2;
            const float2 x0 = *(const float2*)&x[((size_t)b * CC + m) * SS + n];
            const float2 x1 = *(const float2*)&x[((size_t)b * CC + m + 8) * SS + n];
            float2 v0 = make_float2(acc[mt][nt][0] + bi0 + x0.x, acc[mt][nt][1] + bi0 + x0.y);
            float2 v1 = make_float2(acc[mt][nt][2] + bi1 + x1.x, acc[mt][nt][3] + bi1 + x1.y);
            *(float2*)&out[((size_t)b * CC + m) * SS + n]     = v0;
            *(float2*)&out[((size_t)b * CC + m + 8) * SS + n] = v1;
        }
    }
}

// ---------------------------------------------------------------------------
extern "C" void kernel_launch(void* const* d_in, const int* in_sizes, int n_in,
                              void* d_out, int out_size) {
    const float* x     = (const float*)d_in[0];
    const float* gamma = (const float*)d_in[1];
    const float* wq    = (const float*)d_in[2];
    const float* bq    = (const float*)d_in[3];
    const float* wk    = (const float*)d_in[4];
    const float* bk    = (const float*)d_in[5];
    const float* wv    = (const float*)d_in[6];
    const float* bv    = (const float*)d_in[7];
    const float* wo    = (const float*)d_in[8];
    const float* bo    = (const float*)d_in[9];
    float* out = (float*)d_out;

    static int attr_done = 0;
    if (!attr_done) {
        cudaFuncSetAttribute(proj_qk_kernel, cudaFuncAttributeMaxDynamicSharedMemorySize, SMEM_GEMM);
        cudaFuncSetAttribute(proj_v_kernel,  cudaFuncAttributeMaxDynamicSharedMemorySize, SMEM_GEMM);
        cudaFuncSetAttribute(qk_kernel,      cudaFuncAttributeMaxDynamicSharedMemorySize, SMEM_GEMM);
        cudaFuncSetAttribute(pv_kernel,      cudaFuncAttributeMaxDynamicSharedMemorySize, SMEM_GEMM);
        cudaFuncSetAttribute(oproj_kernel,   cudaFuncAttributeMaxDynamicSharedMemorySize, SMEM_GEMM);
        attr_done = 1;
    }

    prep_w_kernel<<<dim3(CC * CC / 256, 4), 256>>>(wq, wk, wv, wo);
    norm_kernel<<<dim3(SS / 256, BB), 256>>>(x);
    transpose_kernel<<<dim3(CC / 32, SS / 32, BB), 256>>>(x, gamma);
    proj_qk_kernel<<<dim3(SS / 128, CC / 128, BB * 2), 128, SMEM_GEMM>>>(bq, bk);
    proj_v_kernel<<<dim3(SS / 128, CC / 128, BB), 128, SMEM_GEMM>>>(bv);
    qk_kernel<<<dim3(2304, 1, BB), 128, SMEM_GEMM>>>();
    rsum_kernel<<<dim3(SS, BB), 256>>>();
    pv_kernel<<<dim3(CC / 128, SS / 128, BB), 128, SMEM_GEMM>>>();
    oproj_kernel<<<dim3(SS / 128, CC / 128, BB), 128, SMEM_GEMM>>>(bo, x, out);
}

// round 10
// speedup vs baseline: 1.2098x; 1.2098x over previous
#include <cuda_runtime.h>
#include <cuda_bf16.h>
#include <math.h>
#include <stdint.h>

#define BB 2
#define CC 512
#define SS 8192
#define NHW 1024
#define SQRT_C     22.627416997969522f
#define INV_SQRT_C 0.04419417382415922f

// bf16 MK tiles: 128 rows x 64 k bf16, row stride 72 bf16 (144 B)
#define KSLAB 64
#define MKP 72
#define SZ_MK (128 * MKP * 2)    // 18432 B
#define HALF_MK 64               // byte offset of second 32-k half
#define SMEM_GEMM (3 * 2 * SZ_MK)   // 110592 B, 2 CTAs/SM

// Scratch
__device__ float         g_scale[(size_t)BB * SS];
__device__ __nv_bfloat16 g_hn[(size_t)BB * SS * CC];   // [b][s][c]
__device__ __nv_bfloat16 g_q [(size_t)BB * SS * CC];   // [b][s][c]
__device__ __nv_bfloat16 g_k [(size_t)BB * SS * CC];   // [b][s][c]
__device__ __nv_bfloat16 g_v [(size_t)BB * CC * SS];   // [b][c][s]
__device__ __nv_bfloat16 g_p [(size_t)BB * SS * SS];   // [b][sq][sk] (exp, unnormalized)
__device__ __nv_bfloat16 g_o [(size_t)BB * SS * CC];   // [b][s][c]
__device__ __nv_bfloat16 g_w [4][(size_t)CC * CC];     // bf16 weights [co][ci]
__device__ float         g_rsum[(size_t)BB * SS];

// ---------------------------------------------------------------------------
// PTX helpers
// ---------------------------------------------------------------------------
__device__ __forceinline__ uint32_t smaddr(const void* p) {
    return (uint32_t)__cvta_generic_to_shared(p);
}
__device__ __forceinline__ void cp16(uint32_t d, const void* s) {
    asm volatile("cp.async.cg.shared.global [%0], [%1], 16;\n" :: "r"(d), "l"(s));
}
__device__ __forceinline__ void cp_commit() { asm volatile("cp.async.commit_group;\n"); }
template<int N> __device__ __forceinline__ void cp_wait() {
    asm volatile("cp.async.wait_group %0;\n" :: "n"(N));
}
__device__ __forceinline__ void ldsm4(uint32_t* r, uint32_t a) {
    asm volatile("ldmatrix.sync.aligned.m8n8.x4.shared.b16 {%0,%1,%2,%3}, [%4];"
                 : "=r"(r[0]), "=r"(r[1]), "=r"(r[2]), "=r"(r[3]) : "r"(a));
}
__device__ __forceinline__ void mma16816(float* c, const uint32_t* a, const uint32_t* b) {
    asm volatile("mma.sync.aligned.m16n8k16.row.col.f32.bf16.bf16.f32 "
                 "{%0,%1,%2,%3},{%4,%5,%6,%7},{%8,%9},{%0,%1,%2,%3};"
                 : "+f"(c[0]), "+f"(c[1]), "+f"(c[2]), "+f"(c[3])
                 : "r"(a[0]), "r"(a[1]), "r"(a[2]), "r"(a[3]), "r"(b[0]), "r"(b[1]));
}

// ---------------------------------------------------------------------------
// stager: 128x64 bf16 MK tile, 128 threads, 8 x 16B chunks each
// ---------------------------------------------------------------------------
__device__ __forceinline__ void stageMK(uint32_t dst, const __nv_bfloat16* g,
                                        int ld, int r0, int k0, int tid) {
#pragma unroll
    for (int j = 0; j < 8; j++) {
        int c = j * 128 + tid;
        int row = c >> 3, off = (c & 7) << 3;
        cp16(dst + (uint32_t)(row * MKP + off) * 2, g + (size_t)(r0 + row) * ld + k0 + off);
    }
}

// ---------------------------------------------------------------------------
// fragment loaders (warp tile 64x64), non-transposed LDSM only
// ---------------------------------------------------------------------------
__device__ __forceinline__ void fragA_MK(uint32_t a[4][4], uint32_t base,
                                         int wm, int lane, int ks) {
    int g = lane >> 3;
#pragma unroll
    for (int mt = 0; mt < 4; mt++) {
        int row = wm + mt * 16 + ((g & 1) << 3) + (lane & 7);
        int col = ks * 16 + ((g >> 1) << 3);
        ldsm4(a[mt], base + (uint32_t)(row * MKP + col) * 2);
    }
}
__device__ __forceinline__ void fragB_MK(uint32_t b[8][4], uint32_t base, int wn, int lane) {
    int g = lane >> 3;
#pragma unroll
    for (int nt = 0; nt < 8; nt++) {
        int row = wn + nt * 8 + (lane & 7);
        int col = g << 3;
        ldsm4(b[nt], base + (uint32_t)(row * MKP + col) * 2);
    }
}

#define GEMM_VARS                                                     \
    extern __shared__ __align__(16) char dynsm[];                     \
    uint32_t sbase = smaddr(dynsm);                                   \
    int tid = threadIdx.x, lane = tid & 31, wid = tid >> 5;           \
    int wm = (wid >> 1) * 64, wn = (wid & 1) * 64;                    \
    int qr = lane >> 2, qc = lane & 3;                                \
    float acc[4][8][4];                                               \
    _Pragma("unroll") for (int mt = 0; mt < 4; mt++)                  \
    _Pragma("unroll") for (int nt = 0; nt < 8; nt++)                  \
    _Pragma("unroll") for (int i = 0; i < 4; i++) acc[mt][nt][i] = 0.f;

// bf16 32-k half-slab
#define SLAB_BF(baseA, baseB)                                         \
    {                                                                 \
        uint32_t bfr[8][4];                                           \
        fragB_MK(bfr, (baseB), wn, lane);                             \
        _Pragma("unroll")                                             \
        for (int ks = 0; ks < 2; ks++) {                              \
            uint32_t afr[4][4];                                       \
            fragA_MK(afr, (baseA), wm, lane, ks);                     \
            _Pragma("unroll") for (int mt = 0; mt < 4; mt++)          \
            _Pragma("unroll") for (int nt = 0; nt < 8; nt++)          \
                mma16816(acc[mt][nt], afr[mt], &bfr[nt][ks * 2]);     \
        }                                                             \
    }
#define SLAB64_BF(baseA, baseB)                                       \
    SLAB_BF((baseA), (baseB));                                        \
    SLAB_BF((baseA) + HALF_MK, (baseB) + HALF_MK);

#define ROT3(s0, s1, s2) { uint32_t _t = s0; s0 = s1; s1 = s2; s2 = _t; }

// generic 3-stage mainloop over nIt 64-k slabs
#define MAINLOOP3(gA, ldA, rA, gB, ldB, rB, nIt)                      \
    uint32_t a0 = sbase, a1 = a0 + SZ_MK, a2 = a1 + SZ_MK;            \
    uint32_t b0 = sbase + 3 * SZ_MK, b1 = b0 + SZ_MK, b2 = b1 + SZ_MK;\
    stageMK(a0, gA, ldA, rA, 0, tid);                                 \
    stageMK(b0, gB, ldB, rB, 0, tid); cp_commit();                    \
    stageMK(a1, gA, ldA, rA, KSLAB, tid);                             \
    stageMK(b1, gB, ldB, rB, KSLAB, tid); cp_commit();                \
    for (int i = 0; i < (nIt); i++) {                                 \
        cp_wait<1>();                                                 \
        __syncthreads();                                              \
        SLAB64_BF(a0, b0);                                            \
        if (i + 2 < (nIt)) {                                          \
            stageMK(a2, gA, ldA, rA, (i + 2) * KSLAB, tid);           \
            stageMK(b2, gB, ldB, rB, (i + 2) * KSLAB, tid);           \
            cp_commit();                                              \
        }                                                             \
        ROT3(a0, a1, a2); ROT3(b0, b1, b2);                           \
    }

// ---------------------------------------------------------------------------
// prep: fp32 weights -> bf16
// ---------------------------------------------------------------------------
__global__ void prep_w_kernel(const float* __restrict__ wq, const float* __restrict__ wk,
                              const float* __restrict__ wv, const float* __restrict__ wo) {
    int which = blockIdx.y;
    const float* w = which == 0 ? wq : which == 1 ? wk : which == 2 ? wv : wo;
    int i = blockIdx.x * 256 + threadIdx.x;
    g_w[which][i] = __float2bfloat16_rn(w[i]);
}

// ---------------------------------------------------------------------------
// per-token rms scale
// ---------------------------------------------------------------------------
__global__ void norm_kernel(const float* __restrict__ x) {
    int s = blockIdx.x * 256 + threadIdx.x;
    int b = blockIdx.y;
    const float* xb = x + (size_t)b * CC * SS + s;
    float ss = 0.f;
#pragma unroll 8
    for (int c = 0; c < CC; c++) {
        float v = xb[(size_t)c * SS];
        ss += v * v;
    }
    g_scale[b * SS + s] = SQRT_C / fmaxf(sqrtf(ss), 1e-12f);
}

// ---------------------------------------------------------------------------
// transpose x[c][s] -> hn[s][c] bf16, applying scale[s]*gamma[c]
// ---------------------------------------------------------------------------
__global__ void transpose_kernel(const float* __restrict__ x,
                                 const float* __restrict__ gamma) {
    __shared__ float t[32][33];
    int b = blockIdx.z;
    int c0 = blockIdx.x * 32, s0 = blockIdx.y * 32;
    int sx = threadIdx.x & 31, cy = threadIdx.x >> 5;   // 32 x 8
    const float* xb = x + ((size_t)b * CC + c0) * SS + s0;
#pragma unroll
    for (int j = 0; j < 4; j++)
        t[cy + 8 * j][sx] = xb[(size_t)(cy + 8 * j) * SS + sx];
    __syncthreads();
    float gm = gamma[c0 + sx];
#pragma unroll
    for (int j = 0; j < 4; j++) {
        int sr = cy + 8 * j;
        float sc = g_scale[b * SS + s0 + sr];
        g_hn[((size_t)b * SS + s0 + sr) * CC + c0 + sx] =
            __float2bfloat16_rn(t[sx][sr] * sc * gm);
    }
}

// ---------------------------------------------------------------------------
// q/k projection: D[s][co] = hn[s][:] . W[co][:] + bias  -> bf16 [s][c]
// ---------------------------------------------------------------------------
__global__ void __launch_bounds__(128) proj_qk_kernel(
    const float* __restrict__ bq, const float* __restrict__ bk) {

    int z = blockIdx.z, b = z >> 1, which = z & 1;
    const __nv_bfloat16* HN = g_hn + (size_t)b * SS * CC;
    const __nv_bfloat16* W  = g_w[which];
    const float* bias = which ? bk : bq;
    __nv_bfloat16* Qout = (which ? g_k : g_q) + (size_t)b * SS * CC;

    int m0 = blockIdx.x * 128;   // s
    int n0 = blockIdx.y * 128;   // co
    GEMM_VARS
    MAINLOOP3(HN, CC, m0, W, CC, n0, CC / KSLAB)

#pragma unroll
    for (int mt = 0; mt < 4; mt++) {
        int m = m0 + wm + mt * 16 + qr;
#pragma unroll
        for (int nt = 0; nt < 8; nt++) {
            int n = n0 + wn + nt * 8 + qc * 2;
            float bi0 = bias[n], bi1 = bias[n + 1];
            *(__nv_bfloat162*)&Qout[(size_t)m * CC + n] =
                __floats2bfloat162_rn(acc[mt][nt][0] + bi0, acc[mt][nt][1] + bi1);
            *(__nv_bfloat162*)&Qout[(size_t)(m + 8) * CC + n] =
                __floats2bfloat162_rn(acc[mt][nt][2] + bi0, acc[mt][nt][3] + bi1);
        }
    }
}

// ---------------------------------------------------------------------------
// v projection: D[co][s] = W[co][:] . hn[s][:] + bv  -> bf16 [c][s]
// ---------------------------------------------------------------------------
__global__ void __launch_bounds__(128) proj_v_kernel(const float* __restrict__ bv) {
    int b = blockIdx.z;
    int m0 = blockIdx.y * 128;   // co
    int n0 = blockIdx.x * 128;   // s
    const __nv_bfloat16* W  = g_w[2];
    const __nv_bfloat16* HN = g_hn + (size_t)b * SS * CC;
    __nv_bfloat16* Vout = g_v + (size_t)b * CC * SS;
    GEMM_VARS
    MAINLOOP3(W, CC, m0, HN, CC, n0, CC / KSLAB)

#pragma unroll
    for (int mt = 0; mt < 4; mt++) {
        int m = m0 + wm + mt * 16 + qr;
        float bi0 = bv[m], bi1 = bv[m + 8];
#pragma unroll
        for (int nt = 0; nt < 8; nt++) {
            int n = n0 + wn + nt * 8 + qc * 2;
            *(__nv_bfloat162*)&Vout[(size_t)m * SS + n] =
                __floats2bfloat162_rn(acc[mt][nt][0] + bi0, acc[mt][nt][1] + bi0);
            *(__nv_bfloat162*)&Vout[(size_t)(m + 8) * SS + n] =
                __floats2bfloat162_rn(acc[mt][nt][2] + bi1, acc[mt][nt][3] + bi1);
        }
    }
}

// ---------------------------------------------------------------------------
// QK^T (all-MK), compacted grid over allowed tiles; writes exp(scores) bf16
// ---------------------------------------------------------------------------
__global__ void __launch_bounds__(128) qk_kernel() {
    int b = blockIdx.z;
    int bi = blockIdx.x;
    int f = 0;
    while (bi >= 64 * (f + 1)) { bi -= 64 * (f + 1); f++; }
    int r  = bi / (8 * (f + 1));
    int nc = bi % (8 * (f + 1));
    int m0 = (f * 8 + r) * 128;   // sq
    int n0 = nc * 128;            // sk

    const __nv_bfloat16* Q = g_q + (size_t)b * SS * CC;
    const __nv_bfloat16* K = g_k + (size_t)b * SS * CC;
    GEMM_VARS
    MAINLOOP3(Q, CC, m0, K, CC, n0, CC / KSLAB)

    __nv_bfloat16* P = g_p + (size_t)b * SS * SS;
#pragma unroll
    for (int mt = 0; mt < 4; mt++) {
        int m = m0 + wm + mt * 16 + qr;
#pragma unroll
        for (int nt = 0; nt < 8; nt++) {
            int n = n0 + wn + nt * 8 + qc * 2;
            *(__nv_bfloat162*)&P[(size_t)m * SS + n] =
                __floats2bfloat162_rn(__expf(acc[mt][nt][0] * INV_SQRT_C),
                                      __expf(acc[mt][nt][1] * INV_SQRT_C));
            *(__nv_bfloat162*)&P[(size_t)(m + 8) * SS + n] =
                __floats2bfloat162_rn(__expf(acc[mt][nt][2] * INV_SQRT_C),
                                      __expf(acc[mt][nt][3] * INV_SQRT_C));
        }
    }
}

// ---------------------------------------------------------------------------
// row sums of exp(scores)
// ---------------------------------------------------------------------------
__global__ void __launch_bounds__(256) rsum_kernel() {
    int sq = blockIdx.x;
    int b  = blockIdx.y;
    const __nv_bfloat162* row2 = (const __nv_bfloat162*)(g_p + ((size_t)b * SS + sq) * SS);
    int L = (sq / NHW + 1) * NHW;
    int n2 = L >> 9;
    int tid = threadIdx.x, lane = tid & 31, wid = tid >> 5;

    __shared__ float red[8];
    float s = 0.f;
#pragma unroll
    for (int i = 0; i < 16; i++)
        if (i < n2) {
            float2 v = __bfloat1622float2(row2[i * 256 + tid]);
            s += v.x + v.y;
        }
#pragma unroll
    for (int o = 16; o > 0; o >>= 1) s += __shfl_xor_sync(0xffffffffu, s, o);
    if (lane == 0) red[wid] = s;
    __syncthreads();
    if (tid == 0) {
        float S = 0.f;
#pragma unroll
        for (int i = 0; i < 8; i++) S += red[i];
        g_rsum[b * SS + sq] = S;
    }
}

// ---------------------------------------------------------------------------
// PV: D[sq][c] = (P[sq][:L] . v[c][:L]) / rsum[sq]  -> bf16 [s][c]
// ---------------------------------------------------------------------------
__global__ void __launch_bounds__(128) pv_kernel() {
    int b  = blockIdx.z;
    int m0 = blockIdx.y * 128;   // sq
    int n0 = blockIdx.x * 128;   // c
    int L  = (m0 / NHW + 1) * NHW;
    const int nIt = L / KSLAB;

    const __nv_bfloat16* P = g_p + (size_t)b * SS * SS;
    const __nv_bfloat16* V = g_v + (size_t)b * CC * SS;
    GEMM_VARS
    MAINLOOP3(P, SS, m0, V, SS, n0, nIt)

    __nv_bfloat16* O = g_o + (size_t)b * SS * CC;
#pragma unroll
    for (int mt = 0; mt < 4; mt++) {
        int m = m0 + wm + mt * 16 + qr;
        float inv0 = 1.f / g_rsum[b * SS + m];
        float inv1 = 1.f / g_rsum[b * SS + m + 8];
#pragma unroll
        for (int nt = 0; nt < 8; nt++) {
            int n = n0 + wn + nt * 8 + qc * 2;
            *(__nv_bfloat162*)&O[(size_t)m * CC + n] =
                __floats2bfloat162_rn(acc[mt][nt][0] * inv0, acc[mt][nt][1] * inv0);
            *(__nv_bfloat162*)&O[(size_t)(m + 8) * CC + n] =
                __floats2bfloat162_rn(acc[mt][nt][2] * inv1, acc[mt][nt][3] * inv1);
        }
    }
}

// ---------------------------------------------------------------------------
// O-proj + residual (fp32 out): A = wo (MK), B = g_o (MK rows s)
// ---------------------------------------------------------------------------
__global__ void __launch_bounds__(128) oproj_kernel(
    const float* __restrict__ bo, const float* __restrict__ x,
    float* __restrict__ out) {

    int b  = blockIdx.z;
    int m0 = blockIdx.y * 128;   // c_out
    int n0 = blockIdx.x * 128;   // s

    const __nv_bfloat16* W = g_w[3];
    const __nv_bfloat16* O = g_o + (size_t)b * SS * CC;
    GEMM_VARS
    MAINLOOP3(W, CC, m0, O, CC, n0, CC / KSLAB)

#pragma unroll
    for (int mt = 0; mt < 4; mt++) {
        int m = m0 + wm + mt * 16 + qr;
        float bi0 = bo[m], bi1 = bo[m + 8];
#pragma unroll
        for (int nt = 0; nt < 8; nt++) {
            int n = n0 + wn + nt * 8 + qc * 2;
            const float2 x0 = *(const float2*)&x[((size_t)b * CC + m) * SS + n];
            const float2 x1 = *(const float2*)&x[((size_t)b * CC + m + 8) * SS + n];
            float2 v0 = make_float2(acc[mt][nt][0] + bi0 + x0.x, acc[mt][nt][1] + bi0 + x0.y);
            float2 v1 = make_float2(acc[mt][nt][2] + bi1 + x1.x, acc[mt][nt][3] + bi1 + x1.y);
            *(float2*)&out[((size_t)b * CC + m) * SS + n]     = v0;
            *(float2*)&out[((size_t)b * CC + m + 8) * SS + n] = v1;
        }
    }
}

// ---------------------------------------------------------------------------
extern "C" void kernel_launch(void* const* d_in, const int* in_sizes, int n_in,
                              void* d_out, int out_size) {
    const float* x     = (const float*)d_in[0];
    const float* gamma = (const float*)d_in[1];
    const float* wq    = (const float*)d_in[2];
    const float* bq    = (const float*)d_in[3];
    const float* wk    = (const float*)d_in[4];
    const float* bk    = (const float*)d_in[5];
    const float* wv    = (const float*)d_in[6];
    const float* bv    = (const float*)d_in[7];
    const float* wo    = (const float*)d_in[8];
    const float* bo    = (const float*)d_in[9];
    float* out = (float*)d_out;

    static int attr_done = 0;
    if (!attr_done) {
        cudaFuncSetAttribute(proj_qk_kernel, cudaFuncAttributeMaxDynamicSharedMemorySize, SMEM_GEMM);
        cudaFuncSetAttribute(proj_v_kernel,  cudaFuncAttributeMaxDynamicSharedMemorySize, SMEM_GEMM);
        cudaFuncSetAttribute(qk_kernel,      cudaFuncAttributeMaxDynamicSharedMemorySize, SMEM_GEMM);
        cudaFuncSetAttribute(pv_kernel,      cudaFuncAttributeMaxDynamicSharedMemorySize, SMEM_GEMM);
        cudaFuncSetAttribute(oproj_kernel,   cudaFuncAttributeMaxDynamicSharedMemorySize, SMEM_GEMM);
        attr_done = 1;
    }

    prep_w_kernel<<<dim3(CC * CC / 256, 4), 256>>>(wq, wk, wv, wo);
    norm_kernel<<<dim3(SS / 256, BB), 256>>>(x);
    transpose_kernel<<<dim3(CC / 32, SS / 32, BB), 256>>>(x, gamma);
    proj_qk_kernel<<<dim3(SS / 128, CC / 128, BB * 2), 128, SMEM_GEMM>>>(bq, bk);
    proj_v_kernel<<<dim3(SS / 128, CC / 128, BB), 128, SMEM_GEMM>>>(bv);
    qk_kernel<<<dim3(2304, 1, BB), 128, SMEM_GEMM>>>();
    rsum_kernel<<<dim3(SS, BB), 256>>>();
    pv_kernel<<<dim3(CC / 128, SS / 128, BB), 128, SMEM_GEMM>>>();
    oproj_kernel<<<dim3(SS / 128, CC / 128, BB), 128, SMEM_GEMM>>>(bo, x, out);
}

// round 11
// speedup vs baseline: 1.2657x; 1.0462x over previous
#include <cuda_runtime.h>
#include <cuda_bf16.h>
#include <math.h>
#include <stdint.h>

#define BB 2
#define CC 512
#define SS 8192
#define NHW 1024
#define SQRT_C     22.627416997969522f
#define INV_SQRT_C 0.04419417382415922f

// bf16 MK tiles: 128 rows x 64 k bf16, row stride 72 bf16 (144 B)
#define KSLAB 64
#define MKP 72
#define SZ_MK (128 * MKP * 2)    // 18432 B
#define HALF_MK 64               // byte offset of second 32-k half
#define SMEM_GEMM (3 * 2 * SZ_MK)   // 110592 B, 2 CTAs/SM

// Scratch
__device__ float         g_scale[(size_t)BB * SS];
__device__ __nv_bfloat16 g_hn[(size_t)BB * SS * CC];   // [b][s][c]
__device__ __nv_bfloat16 g_q [(size_t)BB * SS * CC];   // [b][s][c]
__device__ __nv_bfloat16 g_k [(size_t)BB * SS * CC];   // [b][s][c]
__device__ __nv_bfloat16 g_v [(size_t)BB * CC * SS];   // [b][c][s]
__device__ __nv_bfloat16 g_p [(size_t)BB * SS * SS];   // [b][sq][sk] (exp, unnormalized)
__device__ __nv_bfloat16 g_o [(size_t)BB * SS * CC];   // [b][s][c]
__device__ __nv_bfloat16 g_w [4][(size_t)CC * CC];     // bf16 weights [co][ci]
__device__ float         g_psum[(size_t)BB * SS * 128]; // per-64col-block partial sums
__device__ float         g_rsum[(size_t)BB * SS];       // row sums of exp

// ---------------------------------------------------------------------------
// PTX helpers
// ---------------------------------------------------------------------------
__device__ __forceinline__ uint32_t smaddr(const void* p) {
    return (uint32_t)__cvta_generic_to_shared(p);
}
__device__ __forceinline__ void cp16(uint32_t d, const void* s) {
    asm volatile("cp.async.cg.shared.global [%0], [%1], 16;\n" :: "r"(d), "l"(s));
}
__device__ __forceinline__ void cp_commit() { asm volatile("cp.async.commit_group;\n"); }
template<int N> __device__ __forceinline__ void cp_wait() {
    asm volatile("cp.async.wait_group %0;\n" :: "n"(N));
}
__device__ __forceinline__ void ldsm4(uint32_t* r, uint32_t a) {
    asm volatile("ldmatrix.sync.aligned.m8n8.x4.shared.b16 {%0,%1,%2,%3}, [%4];"
                 : "=r"(r[0]), "=r"(r[1]), "=r"(r[2]), "=r"(r[3]) : "r"(a));
}
__device__ __forceinline__ void mma16816(float* c, const uint32_t* a, const uint32_t* b) {
    asm volatile("mma.sync.aligned.m16n8k16.row.col.f32.bf16.bf16.f32 "
                 "{%0,%1,%2,%3},{%4,%5,%6,%7},{%8,%9},{%0,%1,%2,%3};"
                 : "+f"(c[0]), "+f"(c[1]), "+f"(c[2]), "+f"(c[3])
                 : "r"(a[0]), "r"(a[1]), "r"(a[2]), "r"(a[3]), "r"(b[0]), "r"(b[1]));
}

// ---------------------------------------------------------------------------
// stager: 128x64 bf16 MK tile, 128 threads, 8 x 16B chunks each
// ---------------------------------------------------------------------------
__device__ __forceinline__ void stageMK(uint32_t dst, const __nv_bfloat16* g,
                                        int ld, int r0, int k0, int tid) {
#pragma unroll
    for (int j = 0; j < 8; j++) {
        int c = j * 128 + tid;
        int row = c >> 3, off = (c & 7) << 3;
        cp16(dst + (uint32_t)(row * MKP + off) * 2, g + (size_t)(r0 + row) * ld + k0 + off);
    }
}

// ---------------------------------------------------------------------------
// fragment loaders (warp tile 64x64), non-transposed LDSM only
// ---------------------------------------------------------------------------
__device__ __forceinline__ void fragA_MK(uint32_t a[4][4], uint32_t base,
                                         int wm, int lane, int ks) {
    int g = lane >> 3;
#pragma unroll
    for (int mt = 0; mt < 4; mt++) {
        int row = wm + mt * 16 + ((g & 1) << 3) + (lane & 7);
        int col = ks * 16 + ((g >> 1) << 3);
        ldsm4(a[mt], base + (uint32_t)(row * MKP + col) * 2);
    }
}
__device__ __forceinline__ void fragB_MK(uint32_t b[8][4], uint32_t base, int wn, int lane) {
    int g = lane >> 3;
#pragma unroll
    for (int nt = 0; nt < 8; nt++) {
        int row = wn + nt * 8 + (lane & 7);
        int col = g << 3;
        ldsm4(b[nt], base + (uint32_t)(row * MKP + col) * 2);
    }
}

#define GEMM_VARS                                                     \
    extern __shared__ __align__(16) char dynsm[];                     \
    uint32_t sbase = smaddr(dynsm);                                   \
    int tid = threadIdx.x, lane = tid & 31, wid = tid >> 5;           \
    int wm = (wid >> 1) * 64, wn = (wid & 1) * 64;                    \
    int qr = lane >> 2, qc = lane & 3;                                \
    float acc[4][8][4];                                               \
    _Pragma("unroll") for (int mt = 0; mt < 4; mt++)                  \
    _Pragma("unroll") for (int nt = 0; nt < 8; nt++)                  \
    _Pragma("unroll") for (int i = 0; i < 4; i++) acc[mt][nt][i] = 0.f;

// bf16 32-k half-slab
#define SLAB_BF(baseA, baseB)                                         \
    {                                                                 \
        uint32_t bfr[8][4];                                           \
        fragB_MK(bfr, (baseB), wn, lane);                             \
        _Pragma("unroll")                                             \
        for (int ks = 0; ks < 2; ks++) {                              \
            uint32_t afr[4][4];                                       \
            fragA_MK(afr, (baseA), wm, lane, ks);                     \
            _Pragma("unroll") for (int mt = 0; mt < 4; mt++)          \
            _Pragma("unroll") for (int nt = 0; nt < 8; nt++)          \
                mma16816(acc[mt][nt], afr[mt], &bfr[nt][ks * 2]);     \
        }                                                             \
    }
#define SLAB64_BF(baseA, baseB)                                       \
    SLAB_BF((baseA), (baseB));                                        \
    SLAB_BF((baseA) + HALF_MK, (baseB) + HALF_MK);

#define ROT3(s0, s1, s2) { uint32_t _t = s0; s0 = s1; s1 = s2; s2 = _t; }

// generic 3-stage mainloop over nIt 64-k slabs
#define MAINLOOP3(gA, ldA, rA, gB, ldB, rB, nIt)                      \
    uint32_t a0 = sbase, a1 = a0 + SZ_MK, a2 = a1 + SZ_MK;            \
    uint32_t b0 = sbase + 3 * SZ_MK, b1 = b0 + SZ_MK, b2 = b1 + SZ_MK;\
    stageMK(a0, gA, ldA, rA, 0, tid);                                 \
    stageMK(b0, gB, ldB, rB, 0, tid); cp_commit();                    \
    stageMK(a1, gA, ldA, rA, KSLAB, tid);                             \
    stageMK(b1, gB, ldB, rB, KSLAB, tid); cp_commit();                \
    for (int i = 0; i < (nIt); i++) {                                 \
        cp_wait<1>();                                                 \
        __syncthreads();                                              \
        SLAB64_BF(a0, b0);                                            \
        if (i + 2 < (nIt)) {                                          \
            stageMK(a2, gA, ldA, rA, (i + 2) * KSLAB, tid);           \
            stageMK(b2, gB, ldB, rB, (i + 2) * KSLAB, tid);           \
            cp_commit();                                              \
        }                                                             \
        ROT3(a0, a1, a2); ROT3(b0, b1, b2);                           \
    }

// ---------------------------------------------------------------------------
// prep: fp32 weights -> bf16
// ---------------------------------------------------------------------------
__global__ void prep_w_kernel(const float* __restrict__ wq, const float* __restrict__ wk,
                              const float* __restrict__ wv, const float* __restrict__ wo) {
    int which = blockIdx.y;
    const float* w = which == 0 ? wq : which == 1 ? wk : which == 2 ? wv : wo;
    int i = blockIdx.x * 256 + threadIdx.x;
    g_w[which][i] = __float2bfloat16_rn(w[i]);
}

// ---------------------------------------------------------------------------
// per-token rms scale
// ---------------------------------------------------------------------------
__global__ void norm_kernel(const float* __restrict__ x) {
    int s = blockIdx.x * 256 + threadIdx.x;
    int b = blockIdx.y;
    const float* xb = x + (size_t)b * CC * SS + s;
    float ss = 0.f;
#pragma unroll 8
    for (int c = 0; c < CC; c++) {
        float v = xb[(size_t)c * SS];
        ss += v * v;
    }
    g_scale[b * SS + s] = SQRT_C / fmaxf(sqrtf(ss), 1e-12f);
}

// ---------------------------------------------------------------------------
// transpose x[c][s] -> hn[s][c] bf16, applying scale[s]*gamma[c]
// ---------------------------------------------------------------------------
__global__ void transpose_kernel(const float* __restrict__ x,
                                 const float* __restrict__ gamma) {
    __shared__ float t[32][33];
    int b = blockIdx.z;
    int c0 = blockIdx.x * 32, s0 = blockIdx.y * 32;
    int sx = threadIdx.x & 31, cy = threadIdx.x >> 5;   // 32 x 8
    const float* xb = x + ((size_t)b * CC + c0) * SS + s0;
#pragma unroll
    for (int j = 0; j < 4; j++)
        t[cy + 8 * j][sx] = xb[(size_t)(cy + 8 * j) * SS + sx];
    __syncthreads();
    float gm = gamma[c0 + sx];
#pragma unroll
    for (int j = 0; j < 4; j++) {
        int sr = cy + 8 * j;
        float sc = g_scale[b * SS + s0 + sr];
        g_hn[((size_t)b * SS + s0 + sr) * CC + c0 + sx] =
            __float2bfloat16_rn(t[sx][sr] * sc * gm);
    }
}

// ---------------------------------------------------------------------------
// q/k projection: D[s][co] = hn[s][:] . W[co][:] + bias  -> bf16 [s][c]
// ---------------------------------------------------------------------------
__global__ void __launch_bounds__(128) proj_qk_kernel(
    const float* __restrict__ bq, const float* __restrict__ bk) {

    int z = blockIdx.z, b = z >> 1, which = z & 1;
    const __nv_bfloat16* HN = g_hn + (size_t)b * SS * CC;
    const __nv_bfloat16* W  = g_w[which];
    const float* bias = which ? bk : bq;
    __nv_bfloat16* Qout = (which ? g_k : g_q) + (size_t)b * SS * CC;

    int m0 = blockIdx.x * 128;   // s
    int n0 = blockIdx.y * 128;   // co
    GEMM_VARS
    MAINLOOP3(HN, CC, m0, W, CC, n0, CC / KSLAB)

#pragma unroll
    for (int mt = 0; mt < 4; mt++) {
        int m = m0 + wm + mt * 16 + qr;
#pragma unroll
        for (int nt = 0; nt < 8; nt++) {
            int n = n0 + wn + nt * 8 + qc * 2;
            float bi0 = bias[n], bi1 = bias[n + 1];
            *(__nv_bfloat162*)&Qout[(size_t)m * CC + n] =
                __floats2bfloat162_rn(acc[mt][nt][0] + bi0, acc[mt][nt][1] + bi1);
            *(__nv_bfloat162*)&Qout[(size_t)(m + 8) * CC + n] =
                __floats2bfloat162_rn(acc[mt][nt][2] + bi0, acc[mt][nt][3] + bi1);
        }
    }
}

// ---------------------------------------------------------------------------
// v projection: D[co][s] = W[co][:] . hn[s][:] + bv  -> bf16 [c][s]
// ---------------------------------------------------------------------------
__global__ void __launch_bounds__(128) proj_v_kernel(const float* __restrict__ bv) {
    int b = blockIdx.z;
    int m0 = blockIdx.y * 128;   // co
    int n0 = blockIdx.x * 128;   // s
    const __nv_bfloat16* W  = g_w[2];
    const __nv_bfloat16* HN = g_hn + (size_t)b * SS * CC;
    __nv_bfloat16* Vout = g_v + (size_t)b * CC * SS;
    GEMM_VARS
    MAINLOOP3(W, CC, m0, HN, CC, n0, CC / KSLAB)

#pragma unroll
    for (int mt = 0; mt < 4; mt++) {
        int m = m0 + wm + mt * 16 + qr;
        float bi0 = bv[m], bi1 = bv[m + 8];
#pragma unroll
        for (int nt = 0; nt < 8; nt++) {
            int n = n0 + wn + nt * 8 + qc * 2;
            *(__nv_bfloat162*)&Vout[(size_t)m * SS + n] =
                __floats2bfloat162_rn(acc[mt][nt][0] + bi0, acc[mt][nt][1] + bi0);
            *(__nv_bfloat162*)&Vout[(size_t)(m + 8) * SS + n] =
                __floats2bfloat162_rn(acc[mt][nt][2] + bi1, acc[mt][nt][3] + bi1);
        }
    }
}

// ---------------------------------------------------------------------------
// QK^T (all-MK), compacted grid; writes exp(scores) bf16 + row-sum partials
// ---------------------------------------------------------------------------
__global__ void __launch_bounds__(128) qk_kernel() {
    int b = blockIdx.z;
    int bi = blockIdx.x;
    int f = 0;
    while (bi >= 64 * (f + 1)) { bi -= 64 * (f + 1); f++; }
    int r  = bi / (8 * (f + 1));
    int nc = bi % (8 * (f + 1));
    int m0 = (f * 8 + r) * 128;   // sq
    int n0 = nc * 128;            // sk

    const __nv_bfloat16* Q = g_q + (size_t)b * SS * CC;
    const __nv_bfloat16* K = g_k + (size_t)b * SS * CC;
    GEMM_VARS
    MAINLOOP3(Q, CC, m0, K, CC, n0, CC / KSLAB)

    __nv_bfloat16* P = g_p + (size_t)b * SS * SS;
    int pidx = (n0 >> 6) + (wn >> 6);     // which 64-col block [0,128)
#pragma unroll
    for (int mt = 0; mt < 4; mt++) {
        int m = m0 + wm + mt * 16 + qr;
        float r0 = 0.f, r1 = 0.f;
#pragma unroll
        for (int nt = 0; nt < 8; nt++) {
            int n = n0 + wn + nt * 8 + qc * 2;
            float e0 = __expf(acc[mt][nt][0] * INV_SQRT_C);
            float e1 = __expf(acc[mt][nt][1] * INV_SQRT_C);
            float e2 = __expf(acc[mt][nt][2] * INV_SQRT_C);
            float e3 = __expf(acc[mt][nt][3] * INV_SQRT_C);
            *(__nv_bfloat162*)&P[(size_t)m * SS + n]       = __floats2bfloat162_rn(e0, e1);
            *(__nv_bfloat162*)&P[(size_t)(m + 8) * SS + n] = __floats2bfloat162_rn(e2, e3);
            r0 += e0 + e1;
            r1 += e2 + e3;
        }
        // reduce across the 4 qc lanes (lane bits 0-1)
        r0 += __shfl_xor_sync(0xffffffffu, r0, 1);
        r0 += __shfl_xor_sync(0xffffffffu, r0, 2);
        r1 += __shfl_xor_sync(0xffffffffu, r1, 1);
        r1 += __shfl_xor_sync(0xffffffffu, r1, 2);
        if (qc == 0) {
            g_psum[((size_t)b * SS + m) * 128 + pidx]     = r0;
            g_psum[((size_t)b * SS + m + 8) * 128 + pidx] = r1;
        }
    }
}

// ---------------------------------------------------------------------------
// fold partial sums -> g_rsum (one warp per row; 4 rows per block)
// ---------------------------------------------------------------------------
__global__ void __launch_bounds__(128) psum_reduce_kernel() {
    int b = blockIdx.y;
    int sq = blockIdx.x * 4 + (threadIdx.x >> 5);
    int lane = threadIdx.x & 31;
    int cnt = ((sq / NHW) + 1) * 16;   // valid partials (16..128)
    const float* p = g_psum + ((size_t)b * SS + sq) * 128;
    float s = 0.f;
#pragma unroll
    for (int j = 0; j < 4; j++) {
        int idx = j * 32 + lane;
        if (idx < cnt) s += p[idx];
    }
#pragma unroll
    for (int o = 16; o > 0; o >>= 1) s += __shfl_xor_sync(0xffffffffu, s, o);
    if (lane == 0) g_rsum[b * SS + sq] = s;
}

// ---------------------------------------------------------------------------
// PV: D[sq][c] = (P[sq][:L] . v[c][:L]) / rsum[sq]  -> bf16 [s][c]
// ---------------------------------------------------------------------------
__global__ void __launch_bounds__(128) pv_kernel() {
    int b  = blockIdx.z;
    int m0 = blockIdx.y * 128;   // sq
    int n0 = blockIdx.x * 128;   // c
    int L  = (m0 / NHW + 1) * NHW;
    const int nIt = L / KSLAB;

    const __nv_bfloat16* P = g_p + (size_t)b * SS * SS;
    const __nv_bfloat16* V = g_v + (size_t)b * CC * SS;
    GEMM_VARS
    MAINLOOP3(P, SS, m0, V, SS, n0, nIt)

    __nv_bfloat16* O = g_o + (size_t)b * SS * CC;
#pragma unroll
    for (int mt = 0; mt < 4; mt++) {
        int m = m0 + wm + mt * 16 + qr;
        float inv0 = 1.f / g_rsum[b * SS + m];
        float inv1 = 1.f / g_rsum[b * SS + m + 8];
#pragma unroll
        for (int nt = 0; nt < 8; nt++) {
            int n = n0 + wn + nt * 8 + qc * 2;
            *(__nv_bfloat162*)&O[(size_t)m * CC + n] =
                __floats2bfloat162_rn(acc[mt][nt][0] * inv0, acc[mt][nt][1] * inv0);
            *(__nv_bfloat162*)&O[(size_t)(m + 8) * CC + n] =
                __floats2bfloat162_rn(acc[mt][nt][2] * inv1, acc[mt][nt][3] * inv1);
        }
    }
}

// ---------------------------------------------------------------------------
// O-proj + residual (fp32 out): A = wo (MK), B = g_o (MK rows s)
// ---------------------------------------------------------------------------
__global__ void __launch_bounds__(128) oproj_kernel(
    const float* __restrict__ bo, const float* __restrict__ x,
    float* __restrict__ out) {

    int b  = blockIdx.z;
    int m0 = blockIdx.y * 128;   // c_out
    int n0 = blockIdx.x * 128;   // s

    const __nv_bfloat16* W = g_w[3];
    const __nv_bfloat16* O = g_o + (size_t)b * SS * CC;
    GEMM_VARS
    MAINLOOP3(W, CC, m0, O, CC, n0, CC / KSLAB)

#pragma unroll
    for (int mt = 0; mt < 4; mt++) {
        int m = m0 + wm + mt * 16 + qr;
        float bi0 = bo[m], bi1 = bo[m + 8];
#pragma unroll
        for (int nt = 0; nt < 8; nt++) {
            int n = n0 + wn + nt * 8 + qc * 2;
            const float2 x0 = *(const float2*)&x[((size_t)b * CC + m) * SS + n];
            const float2 x1 = *(const float2*)&x[((size_t)b * CC + m + 8) * SS + n];
            float2 v0 = make_float2(acc[mt][nt][0] + bi0 + x0.x, acc[mt][nt][1] + bi0 + x0.y);
            float2 v1 = make_float2(acc[mt][nt][2] + bi1 + x1.x, acc[mt][nt][3] + bi1 + x1.y);
            *(float2*)&out[((size_t)b * CC + m) * SS + n]     = v0;
            *(float2*)&out[((size_t)b * CC + m + 8) * SS + n] = v1;
        }
    }
}

// ---------------------------------------------------------------------------
extern "C" void kernel_launch(void* const* d_in, const int* in_sizes, int n_in,
                              void* d_out, int out_size) {
    const float* x     = (const float*)d_in[0];
    const float* gamma = (const float*)d_in[1];
    const float* wq    = (const float*)d_in[2];
    const float* bq    = (const float*)d_in[3];
    const float* wk    = (const float*)d_in[4];
    const float* bk    = (const float*)d_in[5];
    const float* wv    = (const float*)d_in[6];
    const float* bv    = (const float*)d_in[7];
    const float* wo    = (const float*)d_in[8];
    const float* bo    = (const float*)d_in[9];
    float* out = (float*)d_out;

    static int attr_done = 0;
    if (!attr_done) {
        cudaFuncSetAttribute(proj_qk_kernel, cudaFuncAttributeMaxDynamicSharedMemorySize, SMEM_GEMM);
        cudaFuncSetAttribute(proj_v_kernel,  cudaFuncAttributeMaxDynamicSharedMemorySize, SMEM_GEMM);
        cudaFuncSetAttribute(qk_kernel,      cudaFuncAttributeMaxDynamicSharedMemorySize, SMEM_GEMM);
        cudaFuncSetAttribute(pv_kernel,      cudaFuncAttributeMaxDynamicSharedMemorySize, SMEM_GEMM);
        cudaFuncSetAttribute(oproj_kernel,   cudaFuncAttributeMaxDynamicSharedMemorySize, SMEM_GEMM);
        attr_done = 1;
    }

    prep_w_kernel<<<dim3(CC * CC / 256, 4), 256>>>(wq, wk, wv, wo);
    norm_kernel<<<dim3(SS / 256, BB), 256>>>(x);
    transpose_kernel<<<dim3(CC / 32, SS / 32, BB), 256>>>(x, gamma);
    proj_qk_kernel<<<dim3(SS / 128, CC / 128, BB * 2), 128, SMEM_GEMM>>>(bq, bk);
    proj_v_kernel<<<dim3(SS / 128, CC / 128, BB), 128, SMEM_GEMM>>>(bv);
    qk_kernel<<<dim3(2304, 1, BB), 128, SMEM_GEMM>>>();
    psum_reduce_kernel<<<dim3(SS / 4, BB), 128>>>();
    pv_kernel<<<dim3(CC / 128, SS / 128, BB), 128, SMEM_GEMM>>>();
    oproj_kernel<<<dim3(SS / 128, CC / 128, BB), 128, SMEM_GEMM>>>(bo, x, out);
}

// round 12
// speedup vs baseline: 1.2835x; 1.0141x over previous
#include <cuda_runtime.h>
#include <cuda_bf16.h>
#include <math.h>
#include <stdint.h>

#define BB 2
#define CC 512
#define SS 8192
#define NHW 1024
#define SQRT_C     22.627416997969522f
#define INV_SQRT_C 0.04419417382415922f

// bf16 MK tiles: 128 rows x 64 k bf16, row stride 72 bf16 (144 B)
#define KSLAB 64
#define MKP 72
#define SZ_MK (128 * MKP * 2)    // 18432 B
#define HALF_MK 64               // byte offset of second 32-k half
#define SMEM_GEMM (3 * 2 * SZ_MK)   // 110592 B, 2 CTAs/SM

// Scratch
__device__ float         g_scale[(size_t)BB * SS];
__device__ __nv_bfloat16 g_hn[(size_t)BB * SS * CC];   // [b][s][c]  (bf16 x^T, un-normalized)
__device__ __nv_bfloat16 g_q [(size_t)BB * SS * CC];   // [b][s][c]
__device__ __nv_bfloat16 g_k [(size_t)BB * SS * CC];   // [b][s][c]
__device__ __nv_bfloat16 g_v [(size_t)BB * CC * SS];   // [b][c][s]
__device__ __nv_bfloat16 g_p [(size_t)BB * SS * SS];   // [b][sq][sk] (exp, unnormalized)
__device__ __nv_bfloat16 g_o [(size_t)BB * SS * CC];   // [b][s][c]
__device__ __nv_bfloat16 g_w [4][(size_t)CC * CC];     // bf16 weights [co][ci] (gamma folded for q/k/v)
__device__ float         g_psum[(size_t)BB * SS * 128]; // per-64col-block partial sums
__device__ float         g_rsum[(size_t)BB * SS];       // row sums of exp

// ---------------------------------------------------------------------------
// PTX helpers
// ---------------------------------------------------------------------------
__device__ __forceinline__ uint32_t smaddr(const void* p) {
    return (uint32_t)__cvta_generic_to_shared(p);
}
__device__ __forceinline__ void cp16(uint32_t d, const void* s) {
    asm volatile("cp.async.cg.shared.global [%0], [%1], 16;\n" :: "r"(d), "l"(s));
}
__device__ __forceinline__ void cp_commit() { asm volatile("cp.async.commit_group;\n"); }
template<int N> __device__ __forceinline__ void cp_wait() {
    asm volatile("cp.async.wait_group %0;\n" :: "n"(N));
}
__device__ __forceinline__ void ldsm4(uint32_t* r, uint32_t a) {
    asm volatile("ldmatrix.sync.aligned.m8n8.x4.shared.b16 {%0,%1,%2,%3}, [%4];"
                 : "=r"(r[0]), "=r"(r[1]), "=r"(r[2]), "=r"(r[3]) : "r"(a));
}
__device__ __forceinline__ void mma16816(float* c, const uint32_t* a, const uint32_t* b) {
    asm volatile("mma.sync.aligned.m16n8k16.row.col.f32.bf16.bf16.f32 "
                 "{%0,%1,%2,%3},{%4,%5,%6,%7},{%8,%9},{%0,%1,%2,%3};"
                 : "+f"(c[0]), "+f"(c[1]), "+f"(c[2]), "+f"(c[3])
                 : "r"(a[0]), "r"(a[1]), "r"(a[2]), "r"(a[3]), "r"(b[0]), "r"(b[1]));
}

// ---------------------------------------------------------------------------
// stager: 128x64 bf16 MK tile, 128 threads, 8 x 16B chunks each
// ---------------------------------------------------------------------------
__device__ __forceinline__ void stageMK(uint32_t dst, const __nv_bfloat16* g,
                                        int ld, int r0, int k0, int tid) {
#pragma unroll
    for (int j = 0; j < 8; j++) {
        int c = j * 128 + tid;
        int row = c >> 3, off = (c & 7) << 3;
        cp16(dst + (uint32_t)(row * MKP + off) * 2, g + (size_t)(r0 + row) * ld + k0 + off);
    }
}

// ---------------------------------------------------------------------------
// fragment loaders (warp tile 64x64), non-transposed LDSM only
// ---------------------------------------------------------------------------
__device__ __forceinline__ void fragA_MK(uint32_t a[4][4], uint32_t base,
                                         int wm, int lane, int ks) {
    int g = lane >> 3;
#pragma unroll
    for (int mt = 0; mt < 4; mt++) {
        int row = wm + mt * 16 + ((g & 1) << 3) + (lane & 7);
        int col = ks * 16 + ((g >> 1) << 3);
        ldsm4(a[mt], base + (uint32_t)(row * MKP + col) * 2);
    }
}
__device__ __forceinline__ void fragB_MK(uint32_t b[8][4], uint32_t base, int wn, int lane) {
    int g = lane >> 3;
#pragma unroll
    for (int nt = 0; nt < 8; nt++) {
        int row = wn + nt * 8 + (lane & 7);
        int col = g << 3;
        ldsm4(b[nt], base + (uint32_t)(row * MKP + col) * 2);
    }
}

#define GEMM_VARS                                                     \
    extern __shared__ __align__(16) char dynsm[];                     \
    uint32_t sbase = smaddr(dynsm);                                   \
    int tid = threadIdx.x, lane = tid & 31, wid = tid >> 5;           \
    int wm = (wid >> 1) * 64, wn = (wid & 1) * 64;                    \
    int qr = lane >> 2, qc = lane & 3;                                \
    float acc[4][8][4];                                               \
    _Pragma("unroll") for (int mt = 0; mt < 4; mt++)                  \
    _Pragma("unroll") for (int nt = 0; nt < 8; nt++)                  \
    _Pragma("unroll") for (int i = 0; i < 4; i++) acc[mt][nt][i] = 0.f;

// bf16 32-k half-slab
#define SLAB_BF(baseA, baseB)                                         \
    {                                                                 \
        uint32_t bfr[8][4];                                           \
        fragB_MK(bfr, (baseB), wn, lane);                             \
        _Pragma("unroll")                                             \
        for (int ks = 0; ks < 2; ks++) {                              \
            uint32_t afr[4][4];                                       \
            fragA_MK(afr, (baseA), wm, lane, ks);                     \
            _Pragma("unroll") for (int mt = 0; mt < 4; mt++)          \
            _Pragma("unroll") for (int nt = 0; nt < 8; nt++)          \
                mma16816(acc[mt][nt], afr[mt], &bfr[nt][ks * 2]);     \
        }                                                             \
    }
#define SLAB64_BF(baseA, baseB)                                       \
    SLAB_BF((baseA), (baseB));                                        \
    SLAB_BF((baseA) + HALF_MK, (baseB) + HALF_MK);

#define ROT3(s0, s1, s2) { uint32_t _t = s0; s0 = s1; s1 = s2; s2 = _t; }

// generic 3-stage mainloop over nIt 64-k slabs
#define MAINLOOP3(gA, ldA, rA, gB, ldB, rB, nIt)                      \
    uint32_t a0 = sbase, a1 = a0 + SZ_MK, a2 = a1 + SZ_MK;            \
    uint32_t b0 = sbase + 3 * SZ_MK, b1 = b0 + SZ_MK, b2 = b1 + SZ_MK;\
    stageMK(a0, gA, ldA, rA, 0, tid);                                 \
    stageMK(b0, gB, ldB, rB, 0, tid); cp_commit();                    \
    stageMK(a1, gA, ldA, rA, KSLAB, tid);                             \
    stageMK(b1, gB, ldB, rB, KSLAB, tid); cp_commit();                \
    for (int i = 0; i < (nIt); i++) {                                 \
        cp_wait<1>();                                                 \
        __syncthreads();                                              \
        SLAB64_BF(a0, b0);                                            \
        if (i + 2 < (nIt)) {                                          \
            stageMK(a2, gA, ldA, rA, (i + 2) * KSLAB, tid);           \
            stageMK(b2, gB, ldB, rB, (i + 2) * KSLAB, tid);           \
            cp_commit();                                              \
        }                                                             \
        ROT3(a0, a1, a2); ROT3(b0, b1, b2);                           \
    }

// ---------------------------------------------------------------------------
// prep: fp32 weights -> bf16; gamma folded into q/k/v weights
// ---------------------------------------------------------------------------
__global__ void prep_w_kernel(const float* __restrict__ wq, const float* __restrict__ wk,
                              const float* __restrict__ wv, const float* __restrict__ wo,
                              const float* __restrict__ gamma) {
    int which = blockIdx.y;
    const float* w = which == 0 ? wq : which == 1 ? wk : which == 2 ? wv : wo;
    int i = blockIdx.x * 256 + threadIdx.x;
    float gm = (which < 3) ? gamma[i & (CC - 1)] : 1.f;
    g_w[which][i] = __float2bfloat16_rn(w[i] * gm);
}

// ---------------------------------------------------------------------------
// per-token rms scale
// ---------------------------------------------------------------------------
__global__ void norm_kernel(const float* __restrict__ x) {
    int s = blockIdx.x * 256 + threadIdx.x;
    int b = blockIdx.y;
    const float* xb = x + (size_t)b * CC * SS + s;
    float ss = 0.f;
#pragma unroll 8
    for (int c = 0; c < CC; c++) {
        float v = xb[(size_t)c * SS];
        ss += v * v;
    }
    g_scale[b * SS + s] = SQRT_C / fmaxf(sqrtf(ss), 1e-12f);
}

// ---------------------------------------------------------------------------
// transpose x[c][s] -> hn[s][c] bf16 (plain; scale applied in proj epilogues)
// ---------------------------------------------------------------------------
__global__ void transpose_kernel(const float* __restrict__ x) {
    __shared__ float t[32][33];
    int b = blockIdx.z;
    int c0 = blockIdx.x * 32, s0 = blockIdx.y * 32;
    int sx = threadIdx.x & 31, cy = threadIdx.x >> 5;   // 32 x 8
    const float* xb = x + ((size_t)b * CC + c0) * SS + s0;
#pragma unroll
    for (int j = 0; j < 4; j++)
        t[cy + 8 * j][sx] = xb[(size_t)(cy + 8 * j) * SS + sx];
    __syncthreads();
#pragma unroll
    for (int j = 0; j < 4; j++) {
        int sr = cy + 8 * j;
        g_hn[((size_t)b * SS + s0 + sr) * CC + c0 + sx] =
            __float2bfloat16_rn(t[sx][sr]);
    }
}

// ---------------------------------------------------------------------------
// q/k projection: D[s][co] = scale[s]*(x^T[s][:] . W'[co][:]) + bias
// ---------------------------------------------------------------------------
__global__ void __launch_bounds__(128) proj_qk_kernel(
    const float* __restrict__ bq, const float* __restrict__ bk) {

    int z = blockIdx.z, b = z >> 1, which = z & 1;
    const __nv_bfloat16* HN = g_hn + (size_t)b * SS * CC;
    const __nv_bfloat16* W  = g_w[which];
    const float* bias = which ? bk : bq;
    __nv_bfloat16* Qout = (which ? g_k : g_q) + (size_t)b * SS * CC;

    int m0 = blockIdx.x * 128;   // s
    int n0 = blockIdx.y * 128;   // co
    GEMM_VARS
    MAINLOOP3(HN, CC, m0, W, CC, n0, CC / KSLAB)

#pragma unroll
    for (int mt = 0; mt < 4; mt++) {
        int m = m0 + wm + mt * 16 + qr;
        float scm0 = g_scale[b * SS + m];
        float scm1 = g_scale[b * SS + m + 8];
#pragma unroll
        for (int nt = 0; nt < 8; nt++) {
            int n = n0 + wn + nt * 8 + qc * 2;
            float bi0 = bias[n], bi1 = bias[n + 1];
            *(__nv_bfloat162*)&Qout[(size_t)m * CC + n] =
                __floats2bfloat162_rn(acc[mt][nt][0] * scm0 + bi0,
                                      acc[mt][nt][1] * scm0 + bi1);
            *(__nv_bfloat162*)&Qout[(size_t)(m + 8) * CC + n] =
                __floats2bfloat162_rn(acc[mt][nt][2] * scm1 + bi0,
                                      acc[mt][nt][3] * scm1 + bi1);
        }
    }
}

// ---------------------------------------------------------------------------
// v projection: D[co][s] = scale[s]*(W'[co][:] . x^T[s][:]) + bv  -> bf16 [c][s]
// ---------------------------------------------------------------------------
__global__ void __launch_bounds__(128) proj_v_kernel(const float* __restrict__ bv) {
    int b = blockIdx.z;
    int m0 = blockIdx.y * 128;   // co
    int n0 = blockIdx.x * 128;   // s
    const __nv_bfloat16* W  = g_w[2];
    const __nv_bfloat16* HN = g_hn + (size_t)b * SS * CC;
    __nv_bfloat16* Vout = g_v + (size_t)b * CC * SS;
    GEMM_VARS
    MAINLOOP3(W, CC, m0, HN, CC, n0, CC / KSLAB)

#pragma unroll
    for (int mt = 0; mt < 4; mt++) {
        int m = m0 + wm + mt * 16 + qr;
        float bi0 = bv[m], bi1 = bv[m + 8];
#pragma unroll
        for (int nt = 0; nt < 8; nt++) {
            int n = n0 + wn + nt * 8 + qc * 2;
            float scn0 = g_scale[b * SS + n];
            float scn1 = g_scale[b * SS + n + 1];
            *(__nv_bfloat162*)&Vout[(size_t)m * SS + n] =
                __floats2bfloat162_rn(acc[mt][nt][0] * scn0 + bi0,
                                      acc[mt][nt][1] * scn1 + bi0);
            *(__nv_bfloat162*)&Vout[(size_t)(m + 8) * SS + n] =
                __floats2bfloat162_rn(acc[mt][nt][2] * scn0 + bi1,
                                      acc[mt][nt][3] * scn1 + bi1);
        }
    }
}

// ---------------------------------------------------------------------------
// QK^T (all-MK), compacted grid; writes exp(scores) bf16 + row-sum partials
// ---------------------------------------------------------------------------
__global__ void __launch_bounds__(128) qk_kernel() {
    int b = blockIdx.z;
    int bi = blockIdx.x;
    int f = 0;
    while (bi >= 64 * (f + 1)) { bi -= 64 * (f + 1); f++; }
    int r  = bi / (8 * (f + 1));
    int nc = bi % (8 * (f + 1));
    int m0 = (f * 8 + r) * 128;   // sq
    int n0 = nc * 128;            // sk

    const __nv_bfloat16* Q = g_q + (size_t)b * SS * CC;
    const __nv_bfloat16* K = g_k + (size_t)b * SS * CC;
    GEMM_VARS
    MAINLOOP3(Q, CC, m0, K, CC, n0, CC / KSLAB)

    __nv_bfloat16* P = g_p + (size_t)b * SS * SS;
    int pidx = (n0 >> 6) + (wn >> 6);     // which 64-col block [0,128)
#pragma unroll
    for (int mt = 0; mt < 4; mt++) {
        int m = m0 + wm + mt * 16 + qr;
        float r0 = 0.f, r1 = 0.f;
#pragma unroll
        for (int nt = 0; nt < 8; nt++) {
            int n = n0 + wn + nt * 8 + qc * 2;
            float e0 = __expf(acc[mt][nt][0] * INV_SQRT_C);
            float e1 = __expf(acc[mt][nt][1] * INV_SQRT_C);
            float e2 = __expf(acc[mt][nt][2] * INV_SQRT_C);
            float e3 = __expf(acc[mt][nt][3] * INV_SQRT_C);
            *(__nv_bfloat162*)&P[(size_t)m * SS + n]       = __floats2bfloat162_rn(e0, e1);
            *(__nv_bfloat162*)&P[(size_t)(m + 8) * SS + n] = __floats2bfloat162_rn(e2, e3);
            r0 += e0 + e1;
            r1 += e2 + e3;
        }
        r0 += __shfl_xor_sync(0xffffffffu, r0, 1);
        r0 += __shfl_xor_sync(0xffffffffu, r0, 2);
        r1 += __shfl_xor_sync(0xffffffffu, r1, 1);
        r1 += __shfl_xor_sync(0xffffffffu, r1, 2);
        if (qc == 0) {
            g_psum[((size_t)b * SS + m) * 128 + pidx]     = r0;
            g_psum[((size_t)b * SS + m + 8) * 128 + pidx] = r1;
        }
    }
}

// ---------------------------------------------------------------------------
// fold partial sums -> g_rsum (one warp per row; 4 rows per block)
// ---------------------------------------------------------------------------
__global__ void __launch_bounds__(128) psum_reduce_kernel() {
    int b = blockIdx.y;
    int sq = blockIdx.x * 4 + (threadIdx.x >> 5);
    int lane = threadIdx.x & 31;
    int cnt = ((sq / NHW) + 1) * 16;   // valid partials (16..128)
    const float* p = g_psum + ((size_t)b * SS + sq) * 128;
    float s = 0.f;
#pragma unroll
    for (int j = 0; j < 4; j++) {
        int idx = j * 32 + lane;
        if (idx < cnt) s += p[idx];
    }
#pragma unroll
    for (int o = 16; o > 0; o >>= 1) s += __shfl_xor_sync(0xffffffffu, s, o);
    if (lane == 0) g_rsum[b * SS + sq] = s;
}

// ---------------------------------------------------------------------------
// PV: D[sq][c] = (P[sq][:L] . v[c][:L]) / rsum[sq]  -> bf16 [s][c]
// ---------------------------------------------------------------------------
__global__ void __launch_bounds__(128) pv_kernel() {
    int b  = blockIdx.z;
    int m0 = blockIdx.y * 128;   // sq
    int n0 = blockIdx.x * 128;   // c
    int L  = (m0 / NHW + 1) * NHW;
    const int nIt = L / KSLAB;

    const __nv_bfloat16* P = g_p + (size_t)b * SS * SS;
    const __nv_bfloat16* V = g_v + (size_t)b * CC * SS;
    GEMM_VARS
    MAINLOOP3(P, SS, m0, V, SS, n0, nIt)

    __nv_bfloat16* O = g_o + (size_t)b * SS * CC;
#pragma unroll
    for (int mt = 0; mt < 4; mt++) {
        int m = m0 + wm + mt * 16 + qr;
        float inv0 = 1.f / g_rsum[b * SS + m];
        float inv1 = 1.f / g_rsum[b * SS + m + 8];
#pragma unroll
        for (int nt = 0; nt < 8; nt++) {
            int n = n0 + wn + nt * 8 + qc * 2;
            *(__nv_bfloat162*)&O[(size_t)m * CC + n] =
                __floats2bfloat162_rn(acc[mt][nt][0] * inv0, acc[mt][nt][1] * inv0);
            *(__nv_bfloat162*)&O[(size_t)(m + 8) * CC + n] =
                __floats2bfloat162_rn(acc[mt][nt][2] * inv1, acc[mt][nt][3] * inv1);
        }
    }
}

// ---------------------------------------------------------------------------
// O-proj + residual (fp32 out): A = wo (MK), B = g_o (MK rows s)
// ---------------------------------------------------------------------------
__global__ void __launch_bounds__(128) oproj_kernel(
    const float* __restrict__ bo, const float* __restrict__ x,
    float* __restrict__ out) {

    int b  = blockIdx.z;
    int m0 = blockIdx.y * 128;   // c_out
    int n0 = blockIdx.x * 128;   // s

    const __nv_bfloat16* W = g_w[3];
    const __nv_bfloat16* O = g_o + (size_t)b * SS * CC;
    GEMM_VARS
    MAINLOOP3(W, CC, m0, O, CC, n0, CC / KSLAB)

#pragma unroll
    for (int mt = 0; mt < 4; mt++) {
        int m = m0 + wm + mt * 16 + qr;
        float bi0 = bo[m], bi1 = bo[m + 8];
#pragma unroll
        for (int nt = 0; nt < 8; nt++) {
            int n = n0 + wn + nt * 8 + qc * 2;
            const float2 x0 = *(const float2*)&x[((size_t)b * CC + m) * SS + n];
            const float2 x1 = *(const float2*)&x[((size_t)b * CC + m + 8) * SS + n];
            float2 v0 = make_float2(acc[mt][nt][0] + bi0 + x0.x, acc[mt][nt][1] + bi0 + x0.y);
            float2 v1 = make_float2(acc[mt][nt][2] + bi1 + x1.x, acc[mt][nt][3] + bi1 + x1.y);
            *(float2*)&out[((size_t)b * CC + m) * SS + n]     = v0;
            *(float2*)&out[((size_t)b * CC + m + 8) * SS + n] = v1;
        }
    }
}

// ---------------------------------------------------------------------------
extern "C" void kernel_launch(void* const* d_in, const int* in_sizes, int n_in,
                              void* d_out, int out_size) {
    const float* x     = (const float*)d_in[0];
    const float* gamma = (const float*)d_in[1];
    const float* wq    = (const float*)d_in[2];
    const float* bq    = (const float*)d_in[3];
    const float* wk    = (const float*)d_in[4];
    const float* bk    = (const float*)d_in[5];
    const float* wv    = (const float*)d_in[6];
    const float* bv    = (const float*)d_in[7];
    const float* wo    = (const float*)d_in[8];
    const float* bo    = (const float*)d_in[9];
    float* out = (float*)d_out;

    static cudaStream_t s1 = nullptr;
    static cudaEvent_t evFork, evS1, evTrans, evProjV;
    if (!s1) {
        cudaStreamCreateWithFlags(&s1, cudaStreamNonBlocking);
        cudaEventCreateWithFlags(&evFork,  cudaEventDisableTiming);
        cudaEventCreateWithFlags(&evS1,    cudaEventDisableTiming);
        cudaEventCreateWithFlags(&evTrans, cudaEventDisableTiming);
        cudaEventCreateWithFlags(&evProjV, cudaEventDisableTiming);
        cudaFuncSetAttribute(proj_qk_kernel, cudaFuncAttributeMaxDynamicSharedMemorySize, SMEM_GEMM);
        cudaFuncSetAttribute(proj_v_kernel,  cudaFuncAttributeMaxDynamicSharedMemorySize, SMEM_GEMM);
        cudaFuncSetAttribute(qk_kernel,      cudaFuncAttributeMaxDynamicSharedMemorySize, SMEM_GEMM);
        cudaFuncSetAttribute(pv_kernel,      cudaFuncAttributeMaxDynamicSharedMemorySize, SMEM_GEMM);
        cudaFuncSetAttribute(oproj_kernel,   cudaFuncAttributeMaxDynamicSharedMemorySize, SMEM_GEMM);
    }

    // fork: s1 does prep_w + norm while stream 0 does the transpose
    cudaEventRecord(evFork, 0);
    cudaStreamWaitEvent(s1, evFork, 0);
    prep_w_kernel<<<dim3(CC * CC / 256, 4), 256, 0, s1>>>(wq, wk, wv, wo, gamma);
    norm_kernel<<<dim3(SS / 256, BB), 256, 0, s1>>>(x);
    cudaEventRecord(evS1, s1);

    transpose_kernel<<<dim3(CC / 32, SS / 32, BB), 256>>>(x);
    cudaEventRecord(evTrans, 0);

    // proj_qk on stream 0 (needs transpose [s0 order] + prep/norm [evS1])
    cudaStreamWaitEvent(0, evS1, 0);
    proj_qk_kernel<<<dim3(SS / 128, CC / 128, BB * 2), 128, SMEM_GEMM>>>(bq, bk);

    // proj_v on s1 (needs prep/norm [s1 order] + transpose [evTrans])
    cudaStreamWaitEvent(s1, evTrans, 0);
    proj_v_kernel<<<dim3(SS / 128, CC / 128, BB), 128, SMEM_GEMM, s1>>>(bv);
    cudaEventRecord(evProjV, s1);

    // join, then the serial attention chain on stream 0
    cudaStreamWaitEvent(0, evProjV, 0);
    qk_kernel<<<dim3(2304, 1, BB), 128, SMEM_GEMM>>>();
    psum_reduce_kernel<<<dim3(SS / 4, BB), 128>>>();
    pv_kernel<<<dim3(CC / 128, SS / 128, BB), 128, SMEM_GEMM>>>();
    oproj_kernel<<<dim3(SS / 128, CC / 128, BB), 128, SMEM_GEMM>>>(bo, x, out);
}

// round 14
// speedup vs baseline: 1.3243x; 1.0318x over previous
#include <cuda_runtime.h>
#include <cuda_bf16.h>
#include <math.h>
#include <stdint.h>

#define BB 2
#define CC 512
#define SS 8192
#define NHW 1024
#define SQRT_C     22.627416997969522f
#define INV_SQRT_C 0.04419417382415922f

// bf16 MK tiles: 128 rows x 64 k bf16, row stride 72 bf16 (144 B)
#define KSLAB 64
#define MKP 72
#define SZ_MK (128 * MKP * 2)    // 18432 B
#define HALF_MK 64               // byte offset of second 32-k half
#define SMEM_GEMM (3 * 2 * SZ_MK)   // 110592 B, 2 CTAs/SM
#define SMEM_NT   (512 * 33 * 4)    // 67584 B for norm+transpose staging

// Scratch
__device__ float         g_scale[(size_t)BB * SS];
__device__ __nv_bfloat16 g_hn[(size_t)BB * SS * CC];   // [b][s][c]  (bf16 x^T, un-normalized)
__device__ __nv_bfloat16 g_q [(size_t)BB * SS * CC];   // [b][s][c]
__device__ __nv_bfloat16 g_k [(size_t)BB * SS * CC];   // [b][s][c]
__device__ __nv_bfloat16 g_v [(size_t)BB * CC * SS];   // [b][c][s]
__device__ __nv_bfloat16 g_p [(size_t)BB * SS * SS];   // [b][sq][sk] (exp, unnormalized)
__device__ __nv_bfloat16 g_o [(size_t)BB * SS * CC];   // [b][s][c]
__device__ __nv_bfloat16 g_w [4][(size_t)CC * CC];     // bf16 weights [co][ci] (gamma folded for q/k/v)
__device__ float         g_psum[(size_t)BB * SS * 128]; // per-64col-block partial sums
__device__ float         g_rsum[(size_t)BB * SS];       // row sums of exp

// ---------------------------------------------------------------------------
// PTX helpers
// ---------------------------------------------------------------------------
__device__ __forceinline__ uint32_t smaddr(const void* p) {
    return (uint32_t)__cvta_generic_to_shared(p);
}
__device__ __forceinline__ void cp16(uint32_t d, const void* s) {
    asm volatile("cp.async.cg.shared.global [%0], [%1], 16;\n" :: "r"(d), "l"(s));
}
__device__ __forceinline__ void cp_commit() { asm volatile("cp.async.commit_group;\n"); }
template<int N> __device__ __forceinline__ void cp_wait() {
    asm volatile("cp.async.wait_group %0;\n" :: "n"(N));
}
__device__ __forceinline__ void ldsm4(uint32_t* r, uint32_t a) {
    asm volatile("ldmatrix.sync.aligned.m8n8.x4.shared.b16 {%0,%1,%2,%3}, [%4];"
                 : "=r"(r[0]), "=r"(r[1]), "=r"(r[2]), "=r"(r[3]) : "r"(a));
}
__device__ __forceinline__ void mma16816(float* c, const uint32_t* a, const uint32_t* b) {
    asm volatile("mma.sync.aligned.m16n8k16.row.col.f32.bf16.bf16.f32 "
                 "{%0,%1,%2,%3},{%4,%5,%6,%7},{%8,%9},{%0,%1,%2,%3};"
                 : "+f"(c[0]), "+f"(c[1]), "+f"(c[2]), "+f"(c[3])
                 : "r"(a[0]), "r"(a[1]), "r"(a[2]), "r"(a[3]), "r"(b[0]), "r"(b[1]));
}

// ---------------------------------------------------------------------------
// stager: 128x64 bf16 MK tile, 128 threads, 8 x 16B chunks each
// ---------------------------------------------------------------------------
__device__ __forceinline__ void stageMK(uint32_t dst, const __nv_bfloat16* g,
                                        int ld, int r0, int k0, int tid) {
#pragma unroll
    for (int j = 0; j < 8; j++) {
        int c = j * 128 + tid;
        int row = c >> 3, off = (c & 7) << 3;
        cp16(dst + (uint32_t)(row * MKP + off) * 2, g + (size_t)(r0 + row) * ld + k0 + off);
    }
}

// ---------------------------------------------------------------------------
// fragment loaders (warp tile 64x64), non-transposed LDSM only
// ---------------------------------------------------------------------------
__device__ __forceinline__ void fragA_MK(uint32_t a[4][4], uint32_t base,
                                         int wm, int lane, int ks) {
    int g = lane >> 3;
#pragma unroll
    for (int mt = 0; mt < 4; mt++) {
        int row = wm + mt * 16 + ((g & 1) << 3) + (lane & 7);
        int col = ks * 16 + ((g >> 1) << 3);
        ldsm4(a[mt], base + (uint32_t)(row * MKP + col) * 2);
    }
}
__device__ __forceinline__ void fragB_MK(uint32_t b[8][4], uint32_t base, int wn, int lane) {
    int g = lane >> 3;
#pragma unroll
    for (int nt = 0; nt < 8; nt++) {
        int row = wn + nt * 8 + (lane & 7);
        int col = g << 3;
        ldsm4(b[nt], base + (uint32_t)(row * MKP + col) * 2);
    }
}

#define GEMM_VARS                                                     \
    extern __shared__ __align__(16) char dynsm[];                     \
    uint32_t sbase = smaddr(dynsm);                                   \
    int tid = threadIdx.x, lane = tid & 31, wid = tid >> 5;           \
    int wm = (wid >> 1) * 64, wn = (wid & 1) * 64;                    \
    int qr = lane >> 2, qc = lane & 3;                                \
    float acc[4][8][4];                                               \
    _Pragma("unroll") for (int mt = 0; mt < 4; mt++)                  \
    _Pragma("unroll") for (int nt = 0; nt < 8; nt++)                  \
    _Pragma("unroll") for (int i = 0; i < 4; i++) acc[mt][nt][i] = 0.f;

// bf16 32-k half-slab
#define SLAB_BF(baseA, baseB)                                         \
    {                                                                 \
        uint32_t bfr[8][4];                                           \
        fragB_MK(bfr, (baseB), wn, lane);                             \
        _Pragma("unroll")                                             \
        for (int ks = 0; ks < 2; ks++) {                              \
            uint32_t afr[4][4];                                       \
            fragA_MK(afr, (baseA), wm, lane, ks);                     \
            _Pragma("unroll") for (int mt = 0; mt < 4; mt++)          \
            _Pragma("unroll") for (int nt = 0; nt < 8; nt++)          \
                mma16816(acc[mt][nt], afr[mt], &bfr[nt][ks * 2]);     \
        }                                                             \
    }
#define SLAB64_BF(baseA, baseB)                                       \
    SLAB_BF((baseA), (baseB));                                        \
    SLAB_BF((baseA) + HALF_MK, (baseB) + HALF_MK);

#define ROT3(s0, s1, s2) { uint32_t _t = s0; s0 = s1; s1 = s2; s2 = _t; }

// generic 3-stage mainloop over nIt 64-k slabs
#define MAINLOOP3(gA, ldA, rA, gB, ldB, rB, nIt)                      \
    uint32_t a0 = sbase, a1 = a0 + SZ_MK, a2 = a1 + SZ_MK;            \
    uint32_t b0 = sbase + 3 * SZ_MK, b1 = b0 + SZ_MK, b2 = b1 + SZ_MK;\
    stageMK(a0, gA, ldA, rA, 0, tid);                                 \
    stageMK(b0, gB, ldB, rB, 0, tid); cp_commit();                    \
    stageMK(a1, gA, ldA, rA, KSLAB, tid);                             \
    stageMK(b1, gB, ldB, rB, KSLAB, tid); cp_commit();                \
    for (int i = 0; i < (nIt); i++) {                                 \
        cp_wait<1>();                                                 \
        __syncthreads();                                              \
        SLAB64_BF(a0, b0);                                            \
        if (i + 2 < (nIt)) {                                          \
            stageMK(a2, gA, ldA, rA, (i + 2) * KSLAB, tid);           \
            stageMK(b2, gB, ldB, rB, (i + 2) * KSLAB, tid);           \
            cp_commit();                                              \
        }                                                             \
        ROT3(a0, a1, a2); ROT3(b0, b1, b2);                           \
    }

// ---------------------------------------------------------------------------
// prep: fp32 weights -> bf16; gamma folded into q/k/v weights
// ---------------------------------------------------------------------------
__global__ void prep_w_kernel(const float* __restrict__ wq, const float* __restrict__ wk,
                              const float* __restrict__ wv, const float* __restrict__ wo,
                              const float* __restrict__ gamma) {
    int which = blockIdx.y;
    const float* w = which == 0 ? wq : which == 1 ? wk : which == 2 ? wv : wo;
    int i = blockIdx.x * 256 + threadIdx.x;
    float gm = (which < 3) ? gamma[i & (CC - 1)] : 1.f;
    g_w[which][i] = __float2bfloat16_rn(w[i] * gm);
}

// ---------------------------------------------------------------------------
// fused norm + transpose: reads x once; writes g_scale and plain bf16 x^T
// CTA: 32 s-columns x all 512 channels staged in smem [c][s] (stride 33)
// Staging via scalar ld/st (no 16B alignment requirement; fully coalesced).
// ---------------------------------------------------------------------------
__global__ void __launch_bounds__(256) normtrans_kernel(const float* __restrict__ x) {
    extern __shared__ __align__(16) float sm[];   // 512 x 33 floats
    __shared__ float red[8][32];
    int b  = blockIdx.y;
    int s0 = blockIdx.x * 32;
    int tid = threadIdx.x;

    // stage x[c][s0..s0+32): each 32-thread group loads one 128B row
    const float* xb = x + (size_t)b * CC * SS + s0;
#pragma unroll
    for (int j = 0; j < 64; j++) {
        int idx = j * 256 + tid;
        int c = idx >> 5, s = idx & 31;
        sm[c * 33 + s] = xb[(size_t)c * SS + s];
    }
    __syncthreads();

    // per-s sumsq (8 groups of 64 channels each)
    int g = tid >> 5, s = tid & 31;
    float ss = 0.f;
#pragma unroll 8
    for (int c = g * 64; c < g * 64 + 64; c++) {
        float v = sm[c * 33 + s];
        ss += v * v;
    }
    red[g][s] = ss;
    __syncthreads();
    if (tid < 32) {
        float tot = 0.f;
#pragma unroll
        for (int j = 0; j < 8; j++) tot += red[j][tid];
        g_scale[b * SS + s0 + tid] = SQRT_C / fmaxf(sqrtf(tot), 1e-12f);
    }

    // write transposed bf16 (plain; scale applied in proj epilogues)
    __nv_bfloat16* H = g_hn + ((size_t)b * SS + s0) * CC;
#pragma unroll 4
    for (int row = 0; row < 32; row++) {
        float v0 = sm[(2 * tid)     * 33 + row];
        float v1 = sm[(2 * tid + 1) * 33 + row];
        *(__nv_bfloat162*)&H[(size_t)row * CC + 2 * tid] = __floats2bfloat162_rn(v0, v1);
    }
}

// ---------------------------------------------------------------------------
// merged q/k/v projection. z = b*3 + which.
// q/k: D[s][co] = scale[s]*(x^T . W') + bias  -> [s][c]
// v:   D[co][s] = scale[s]*(W' . x^T) + bv    -> [c][s]
// ---------------------------------------------------------------------------
__global__ void __launch_bounds__(128) proj_kernel(
    const float* __restrict__ bq, const float* __restrict__ bk,
    const float* __restrict__ bv) {

    int z = blockIdx.z, b = z / 3, which = z % 3;
    int bx = blockIdx.x * 128;   // s block
    int by = blockIdx.y * 128;   // co block
    const __nv_bfloat16* HN = g_hn + (size_t)b * SS * CC;
    const __nv_bfloat16* W  = g_w[which];

    const __nv_bfloat16* gA = (which < 2) ? HN + (size_t)bx * CC : W + (size_t)by * CC;
    const __nv_bfloat16* gB = (which < 2) ? W + (size_t)by * CC : HN + (size_t)bx * CC;

    GEMM_VARS
    MAINLOOP3(gA, CC, 0, gB, CC, 0, CC / KSLAB)

    if (which < 2) {
        const float* bias = which ? bk : bq;
        __nv_bfloat16* Qout = (which ? g_k : g_q) + (size_t)b * SS * CC;
#pragma unroll
        for (int mt = 0; mt < 4; mt++) {
            int m = bx + wm + mt * 16 + qr;
            float scm0 = g_scale[b * SS + m];
            float scm1 = g_scale[b * SS + m + 8];
#pragma unroll
            for (int nt = 0; nt < 8; nt++) {
                int n = by + wn + nt * 8 + qc * 2;
                float bi0 = bias[n], bi1 = bias[n + 1];
                *(__nv_bfloat162*)&Qout[(size_t)m * CC + n] =
                    __floats2bfloat162_rn(acc[mt][nt][0] * scm0 + bi0,
                                          acc[mt][nt][1] * scm0 + bi1);
                *(__nv_bfloat162*)&Qout[(size_t)(m + 8) * CC + n] =
                    __floats2bfloat162_rn(acc[mt][nt][2] * scm1 + bi0,
                                          acc[mt][nt][3] * scm1 + bi1);
            }
        }
    } else {
        __nv_bfloat16* Vout = g_v + (size_t)b * CC * SS;
#pragma unroll
        for (int mt = 0; mt < 4; mt++) {
            int m = by + wm + mt * 16 + qr;
            float bi0 = bv[m], bi1 = bv[m + 8];
#pragma unroll
            for (int nt = 0; nt < 8; nt++) {
                int n = bx + wn + nt * 8 + qc * 2;
                float scn0 = g_scale[b * SS + n];
                float scn1 = g_scale[b * SS + n + 1];
                *(__nv_bfloat162*)&Vout[(size_t)m * SS + n] =
                    __floats2bfloat162_rn(acc[mt][nt][0] * scn0 + bi0,
                                          acc[mt][nt][1] * scn1 + bi0);
                *(__nv_bfloat162*)&Vout[(size_t)(m + 8) * SS + n] =
                    __floats2bfloat162_rn(acc[mt][nt][2] * scn0 + bi1,
                                          acc[mt][nt][3] * scn1 + bi1);
            }
        }
    }
}

// ---------------------------------------------------------------------------
// QK^T (all-MK), compacted grid; writes exp(scores) bf16 + row-sum partials
// ---------------------------------------------------------------------------
__global__ void __launch_bounds__(128) qk_kernel() {
    int b = blockIdx.z;
    int bi = blockIdx.x;
    int f = 0;
    while (bi >= 64 * (f + 1)) { bi -= 64 * (f + 1); f++; }
    int r  = bi / (8 * (f + 1));
    int nc = bi % (8 * (f + 1));
    int m0 = (f * 8 + r) * 128;   // sq
    int n0 = nc * 128;            // sk

    const __nv_bfloat16* Q = g_q + (size_t)b * SS * CC;
    const __nv_bfloat16* K = g_k + (size_t)b * SS * CC;
    GEMM_VARS
    MAINLOOP3(Q, CC, m0, K, CC, n0, CC / KSLAB)

    __nv_bfloat16* P = g_p + (size_t)b * SS * SS;
    int pidx = (n0 >> 6) + (wn >> 6);     // which 64-col block [0,128)
#pragma unroll
    for (int mt = 0; mt < 4; mt++) {
        int m = m0 + wm + mt * 16 + qr;
        float r0 = 0.f, r1 = 0.f;
#pragma unroll
        for (int nt = 0; nt < 8; nt++) {
            int n = n0 + wn + nt * 8 + qc * 2;
            float e0 = __expf(acc[mt][nt][0] * INV_SQRT_C);
            float e1 = __expf(acc[mt][nt][1] * INV_SQRT_C);
            float e2 = __expf(acc[mt][nt][2] * INV_SQRT_C);
            float e3 = __expf(acc[mt][nt][3] * INV_SQRT_C);
            *(__nv_bfloat162*)&P[(size_t)m * SS + n]       = __floats2bfloat162_rn(e0, e1);
            *(__nv_bfloat162*)&P[(size_t)(m + 8) * SS + n] = __floats2bfloat162_rn(e2, e3);
            r0 += e0 + e1;
            r1 += e2 + e3;
        }
        r0 += __shfl_xor_sync(0xffffffffu, r0, 1);
        r0 += __shfl_xor_sync(0xffffffffu, r0, 2);
        r1 += __shfl_xor_sync(0xffffffffu, r1, 1);
        r1 += __shfl_xor_sync(0xffffffffu, r1, 2);
        if (qc == 0) {
            g_psum[((size_t)b * SS + m) * 128 + pidx]     = r0;
            g_psum[((size_t)b * SS + m + 8) * 128 + pidx] = r1;
        }
    }
}

// ---------------------------------------------------------------------------
// fold partial sums -> g_rsum (one warp per row; 4 rows per block)
// ---------------------------------------------------------------------------
__global__ void __launch_bounds__(128) psum_reduce_kernel() {
    int b = blockIdx.y;
    int sq = blockIdx.x * 4 + (threadIdx.x >> 5);
    int lane = threadIdx.x & 31;
    int cnt = ((sq / NHW) + 1) * 16;   // valid partials (16..128)
    const float* p = g_psum + ((size_t)b * SS + sq) * 128;
    float s = 0.f;
#pragma unroll
    for (int j = 0; j < 4; j++) {
        int idx = j * 32 + lane;
        if (idx < cnt) s += p[idx];
    }
#pragma unroll
    for (int o = 16; o > 0; o >>= 1) s += __shfl_xor_sync(0xffffffffu, s, o);
    if (lane == 0) g_rsum[b * SS + sq] = s;
}

// ---------------------------------------------------------------------------
// PV: D[sq][c] = (P[sq][:L] . v[c][:L]) / rsum[sq]  -> bf16 [s][c]
// ---------------------------------------------------------------------------
__global__ void __launch_bounds__(128) pv_kernel() {
    int b  = blockIdx.z;
    int m0 = blockIdx.y * 128;   // sq
    int n0 = blockIdx.x * 128;   // c
    int L  = (m0 / NHW + 1) * NHW;
    const int nIt = L / KSLAB;

    const __nv_bfloat16* P = g_p + (size_t)b * SS * SS;
    const __nv_bfloat16* V = g_v + (size_t)b * CC * SS;
    GEMM_VARS
    MAINLOOP3(P, SS, m0, V, SS, n0, nIt)

    __nv_bfloat16* O = g_o + (size_t)b * SS * CC;
#pragma unroll
    for (int mt = 0; mt < 4; mt++) {
        int m = m0 + wm + mt * 16 + qr;
        float inv0 = 1.f / g_rsum[b * SS + m];
        float inv1 = 1.f / g_rsum[b * SS + m + 8];
#pragma unroll
        for (int nt = 0; nt < 8; nt++) {
            int n = n0 + wn + nt * 8 + qc * 2;
            *(__nv_bfloat162*)&O[(size_t)m * CC + n] =
                __floats2bfloat162_rn(acc[mt][nt][0] * inv0, acc[mt][nt][1] * inv0);
            *(__nv_bfloat162*)&O[(size_t)(m + 8) * CC + n] =
                __floats2bfloat162_rn(acc[mt][nt][2] * inv1, acc[mt][nt][3] * inv1);
        }
    }
}

// ---------------------------------------------------------------------------
// O-proj + residual (fp32 out): A = wo (MK), B = g_o (MK rows s)
// ---------------------------------------------------------------------------
__global__ void __launch_bounds__(128) oproj_kernel(
    const float* __restrict__ bo, const float* __restrict__ x,
    float* __restrict__ out) {

    int b  = blockIdx.z;
    int m0 = blockIdx.y * 128;   // c_out
    int n0 = blockIdx.x * 128;   // s

    const __nv_bfloat16* W = g_w[3];
    const __nv_bfloat16* O = g_o + (size_t)b * SS * CC;
    GEMM_VARS
    MAINLOOP3(W, CC, m0, O, CC, n0, CC / KSLAB)

#pragma unroll
    for (int mt = 0; mt < 4; mt++) {
        int m = m0 + wm + mt * 16 + qr;
        float bi0 = bo[m], bi1 = bo[m + 8];
#pragma unroll
        for (int nt = 0; nt < 8; nt++) {
            int n = n0 + wn + nt * 8 + qc * 2;
            const float2 x0 = *(const float2*)&x[((size_t)b * CC + m) * SS + n];
            const float2 x1 = *(const float2*)&x[((size_t)b * CC + m + 8) * SS + n];
            float2 v0 = make_float2(acc[mt][nt][0] + bi0 + x0.x, acc[mt][nt][1] + bi0 + x0.y);
            float2 v1 = make_float2(acc[mt][nt][2] + bi1 + x1.x, acc[mt][nt][3] + bi1 + x1.y);
            *(float2*)&out[((size_t)b * CC + m) * SS + n]     = v0;
            *(float2*)&out[((size_t)b * CC + m + 8) * SS + n] = v1;
        }
    }
}

// ---------------------------------------------------------------------------
extern "C" void kernel_launch(void* const* d_in, const int* in_sizes, int n_in,
                              void* d_out, int out_size) {
    const float* x     = (const float*)d_in[0];
    const float* gamma = (const float*)d_in[1];
    const float* wq    = (const float*)d_in[2];
    const float* bq    = (const float*)d_in[3];
    const float* wk    = (const float*)d_in[4];
    const float* bk    = (const float*)d_in[5];
    const float* wv    = (const float*)d_in[6];
    const float* bv    = (const float*)d_in[7];
    const float* wo    = (const float*)d_in[8];
    const float* bo    = (const float*)d_in[9];
    float* out = (float*)d_out;

    static cudaStream_t s1 = nullptr;
    static cudaEvent_t evFork, evS1;
    if (!s1) {
        cudaStreamCreateWithFlags(&s1, cudaStreamNonBlocking);
        cudaEventCreateWithFlags(&evFork, cudaEventDisableTiming);
        cudaEventCreateWithFlags(&evS1,   cudaEventDisableTiming);
        cudaFuncSetAttribute(normtrans_kernel, cudaFuncAttributeMaxDynamicSharedMemorySize, SMEM_NT);
        cudaFuncSetAttribute(proj_kernel,   cudaFuncAttributeMaxDynamicSharedMemorySize, SMEM_GEMM);
        cudaFuncSetAttribute(qk_kernel,     cudaFuncAttributeMaxDynamicSharedMemorySize, SMEM_GEMM);
        cudaFuncSetAttribute(pv_kernel,     cudaFuncAttributeMaxDynamicSharedMemorySize, SMEM_GEMM);
        cudaFuncSetAttribute(oproj_kernel,  cudaFuncAttributeMaxDynamicSharedMemorySize, SMEM_GEMM);
    }

    // fork: prep_w on s1 while stream 0 does fused norm+transpose
    cudaEventRecord(evFork, 0);
    cudaStreamWaitEvent(s1, evFork, 0);
    prep_w_kernel<<<dim3(CC * CC / 256, 4), 256, 0, s1>>>(wq, wk, wv, wo, gamma);
    cudaEventRecord(evS1, s1);

    normtrans_kernel<<<dim3(SS / 32, BB), 256, SMEM_NT>>>(x);

    // join, then the serial chain on stream 0
    cudaStreamWaitEvent(0, evS1, 0);
    proj_kernel<<<dim3(SS / 128, CC / 128, BB * 3), 128, SMEM_GEMM>>>(bq, bk, bv);
    qk_kernel<<<dim3(2304, 1, BB), 128, SMEM_GEMM>>>();
    psum_reduce_kernel<<<dim3(SS / 4, BB), 128>>>();
    pv_kernel<<<dim3(CC / 128, SS / 128, BB), 128, SMEM_GEMM>>>();
    oproj_kernel<<<dim3(SS / 128, CC / 128, BB), 128, SMEM_GEMM>>>(bo, x, out);
}

// round 15
// speedup vs baseline: 1.3336x; 1.0071x over previous
#include <cuda_runtime.h>
#include <cuda_bf16.h>
#include <math.h>
#include <stdint.h>

#define BB 2
#define CC 512
#define SS 8192
#define NHW 1024
#define SQRT_C     22.627416997969522f
#define INV_SQRT_C 0.04419417382415922f

#define KSLAB 64
#define MKP 72
#define SZ_MK (128 * MKP * 2)    // 18432 B
#define HALF_MK 64
#define SMEM_GEMM (3 * 2 * SZ_MK)   // 110592 B, 2 CTAs/SM
#define SMEM_NT   (512 * 33 * 4)    // 67584 B

// Scratch
__device__ float         g_scale[(size_t)BB * SS];
__device__ __nv_bfloat16 g_hn[(size_t)BB * SS * CC];   // [b][s][c]
__device__ __nv_bfloat16 g_q [(size_t)BB * SS * CC];   // [b][s][c]
__device__ __nv_bfloat16 g_k [(size_t)BB * SS * CC];   // [b][s][c]
__device__ __nv_bfloat16 g_v [(size_t)BB * CC * SS];   // [b][c][s]
__device__ __nv_bfloat16 g_p [(size_t)BB * SS * SS];   // [b][sq][sk] (exp, unnormalized)
__device__ __nv_bfloat16 g_o [(size_t)BB * SS * CC];   // [b][s][c]
__device__ __nv_bfloat16 g_w [4][(size_t)CC * CC];     // bf16 weights (gamma folded q/k/v)
__device__ float         g_psum[(size_t)BB * SS * 128];
__device__ float         g_rsum[(size_t)BB * SS];

// ---------------------------------------------------------------------------
// PTX helpers
// ---------------------------------------------------------------------------
__device__ __forceinline__ uint32_t smaddr(const void* p) {
    return (uint32_t)__cvta_generic_to_shared(p);
}
__device__ __forceinline__ void cp16(uint32_t d, const void* s) {
    asm volatile("cp.async.cg.shared.global [%0], [%1], 16;\n" :: "r"(d), "l"(s));
}
__device__ __forceinline__ void cp_commit() { asm volatile("cp.async.commit_group;\n"); }
template<int N> __device__ __forceinline__ void cp_wait() {
    asm volatile("cp.async.wait_group %0;\n" :: "n"(N));
}
__device__ __forceinline__ void ldsm4(uint32_t* r, uint32_t a) {
    asm volatile("ldmatrix.sync.aligned.m8n8.x4.shared.b16 {%0,%1,%2,%3}, [%4];"
                 : "=r"(r[0]), "=r"(r[1]), "=r"(r[2]), "=r"(r[3]) : "r"(a));
}
__device__ __forceinline__ void mma16816(float* c, const uint32_t* a, const uint32_t* b) {
    asm volatile("mma.sync.aligned.m16n8k16.row.col.f32.bf16.bf16.f32 "
                 "{%0,%1,%2,%3},{%4,%5,%6,%7},{%8,%9},{%0,%1,%2,%3};"
                 : "+f"(c[0]), "+f"(c[1]), "+f"(c[2]), "+f"(c[3])
                 : "r"(a[0]), "r"(a[1]), "r"(a[2]), "r"(a[3]), "r"(b[0]), "r"(b[1]));
}

// ---------------------------------------------------------------------------
// stager: 128x64 bf16 MK tile
// ---------------------------------------------------------------------------
__device__ __forceinline__ void stageMK(uint32_t dst, const __nv_bfloat16* g,
                                        int ld, int k0, int tid) {
#pragma unroll
    for (int j = 0; j < 8; j++) {
        int c = j * 128 + tid;
        int row = c >> 3, off = (c & 7) << 3;
        cp16(dst + (uint32_t)(row * MKP + off) * 2, g + (size_t)row * ld + k0 + off);
    }
}

// ---------------------------------------------------------------------------
// fragment loaders (warp tile 64x64)
// ---------------------------------------------------------------------------
__device__ __forceinline__ void fragA_MK(uint32_t a[4][4], uint32_t base,
                                         int wm, int lane, int ks) {
    int g = lane >> 3;
#pragma unroll
    for (int mt = 0; mt < 4; mt++) {
        int row = wm + mt * 16 + ((g & 1) << 3) + (lane & 7);
        int col = ks * 16 + ((g >> 1) << 3);
        ldsm4(a[mt], base + (uint32_t)(row * MKP + col) * 2);
    }
}
__device__ __forceinline__ void fragB_MK(uint32_t b[8][4], uint32_t base, int wn, int lane) {
    int g = lane >> 3;
#pragma unroll
    for (int nt = 0; nt < 8; nt++) {
        int row = wn + nt * 8 + (lane & 7);
        int col = g << 3;
        ldsm4(b[nt], base + (uint32_t)(row * MKP + col) * 2);
    }
}

#define GEMM_VARS                                                     \
    extern __shared__ __align__(16) char dynsm[];                     \
    uint32_t sbase = smaddr(dynsm);                                   \
    int tid = threadIdx.x, lane = tid & 31, wid = tid >> 5;           \
    int wm = (wid >> 1) * 64, wn = (wid & 1) * 64;                    \
    int qr = lane >> 2, qc = lane & 3;                                \
    float acc[4][8][4];                                               \
    _Pragma("unroll") for (int mt = 0; mt < 4; mt++)                  \
    _Pragma("unroll") for (int nt = 0; nt < 8; nt++)                  \
    _Pragma("unroll") for (int i = 0; i < 4; i++) acc[mt][nt][i] = 0.f;

#define SLAB_BF(baseA, baseB)                                         \
    {                                                                 \
        uint32_t bfr[8][4];                                           \
        fragB_MK(bfr, (baseB), wn, lane);                             \
        _Pragma("unroll")                                             \
        for (int ks = 0; ks < 2; ks++) {                              \
            uint32_t afr[4][4];                                       \
            fragA_MK(afr, (baseA), wm, lane, ks);                     \
            _Pragma("unroll") for (int mt = 0; mt < 4; mt++)          \
            _Pragma("unroll") for (int nt = 0; nt < 8; nt++)          \
                mma16816(acc[mt][nt], afr[mt], &bfr[nt][ks * 2]);     \
        }                                                             \
    }
#define SLAB64_BF(baseA, baseB)                                       \
    SLAB_BF((baseA), (baseB));                                        \
    SLAB_BF((baseA) + HALF_MK, (baseB) + HALF_MK);

#define ROT3(s0, s1, s2) { uint32_t _t = s0; s0 = s1; s1 = s2; s2 = _t; }

// 3-stage mainloop; gA/gB are PRE-OFFSET row pointers
#define MAINLOOP3(gA, ldA, gB, ldB, nIt)                              \
    uint32_t a0 = sbase, a1 = a0 + SZ_MK, a2 = a1 + SZ_MK;            \
    uint32_t b0 = sbase + 3 * SZ_MK, b1 = b0 + SZ_MK, b2 = b1 + SZ_MK;\
    stageMK(a0, gA, ldA, 0, tid);                                     \
    stageMK(b0, gB, ldB, 0, tid); cp_commit();                        \
    stageMK(a1, gA, ldA, KSLAB, tid);                                 \
    stageMK(b1, gB, ldB, KSLAB, tid); cp_commit();                    \
    for (int i = 0; i < (nIt); i++) {                                 \
        cp_wait<1>();                                                 \
        __syncthreads();                                              \
        SLAB64_BF(a0, b0);                                            \
        if (i + 2 < (nIt)) {                                          \
            stageMK(a2, gA, ldA, (i + 2) * KSLAB, tid);               \
            stageMK(b2, gB, ldB, (i + 2) * KSLAB, tid);               \
            cp_commit();                                              \
        }                                                             \
        ROT3(a0, a1, a2); ROT3(b0, b1, b2);                           \
    }

// ---------------------------------------------------------------------------
// prep: fp32 weights -> bf16; gamma folded into q/k/v weights
// ---------------------------------------------------------------------------
__global__ void prep_w_kernel(const float* __restrict__ wq, const float* __restrict__ wk,
                              const float* __restrict__ wv, const float* __restrict__ wo,
                              const float* __restrict__ gamma) {
    int which = blockIdx.y;
    const float* w = which == 0 ? wq : which == 1 ? wk : which == 2 ? wv : wo;
    int i = blockIdx.x * 256 + threadIdx.x;
    float gm = (which < 3) ? gamma[i & (CC - 1)] : 1.f;
    g_w[which][i] = __float2bfloat16_rn(w[i] * gm);
}

// ---------------------------------------------------------------------------
// fused norm + transpose (per batch): reads x once
// ---------------------------------------------------------------------------
__global__ void __launch_bounds__(256) normtrans_kernel(const float* __restrict__ x, int b) {
    extern __shared__ __align__(16) float sm[];   // 512 x 33 floats
    __shared__ float red[8][32];
    int s0 = blockIdx.x * 32;
    int tid = threadIdx.x;

    const float* xb = x + (size_t)b * CC * SS + s0;
#pragma unroll
    for (int j = 0; j < 64; j++) {
        int idx = j * 256 + tid;
        int c = idx >> 5, s = idx & 31;
        sm[c * 33 + s] = xb[(size_t)c * SS + s];
    }
    __syncthreads();

    int g = tid >> 5, s = tid & 31;
    float ss = 0.f;
#pragma unroll 8
    for (int c = g * 64; c < g * 64 + 64; c++) {
        float v = sm[c * 33 + s];
        ss += v * v;
    }
    red[g][s] = ss;
    __syncthreads();
    if (tid < 32) {
        float tot = 0.f;
#pragma unroll
        for (int j = 0; j < 8; j++) tot += red[j][tid];
        g_scale[b * SS + s0 + tid] = SQRT_C / fmaxf(sqrtf(tot), 1e-12f);
    }

    __nv_bfloat16* H = g_hn + ((size_t)b * SS + s0) * CC;
#pragma unroll 4
    for (int row = 0; row < 32; row++) {
        float v0 = sm[(2 * tid)     * 33 + row];
        float v1 = sm[(2 * tid + 1) * 33 + row];
        *(__nv_bfloat162*)&H[(size_t)row * CC + 2 * tid] = __floats2bfloat162_rn(v0, v1);
    }
}

// ---------------------------------------------------------------------------
// merged q/k/v projection (per batch). z = which.
// ---------------------------------------------------------------------------
__global__ void __launch_bounds__(128) proj_kernel(
    const float* __restrict__ bq, const float* __restrict__ bk,
    const float* __restrict__ bv, int b) {

    int which = blockIdx.z;
    int bx = blockIdx.x * 128;   // s block
    int by = blockIdx.y * 128;   // co block
    const __nv_bfloat16* HN = g_hn + (size_t)b * SS * CC;
    const __nv_bfloat16* W  = g_w[which];

    const __nv_bfloat16* gA = (which < 2) ? HN + (size_t)bx * CC : W + (size_t)by * CC;
    const __nv_bfloat16* gB = (which < 2) ? W + (size_t)by * CC : HN + (size_t)bx * CC;

    GEMM_VARS
    MAINLOOP3(gA, CC, gB, CC, CC / KSLAB)

    if (which < 2) {
        const float* bias = which ? bk : bq;
        __nv_bfloat16* Qout = (which ? g_k : g_q) + (size_t)b * SS * CC;
#pragma unroll
        for (int mt = 0; mt < 4; mt++) {
            int m = bx + wm + mt * 16 + qr;
            float scm0 = g_scale[b * SS + m];
            float scm1 = g_scale[b * SS + m + 8];
#pragma unroll
            for (int nt = 0; nt < 8; nt++) {
                int n = by + wn + nt * 8 + qc * 2;
                float bi0 = bias[n], bi1 = bias[n + 1];
                *(__nv_bfloat162*)&Qout[(size_t)m * CC + n] =
                    __floats2bfloat162_rn(acc[mt][nt][0] * scm0 + bi0,
                                          acc[mt][nt][1] * scm0 + bi1);
                *(__nv_bfloat162*)&Qout[(size_t)(m + 8) * CC + n] =
                    __floats2bfloat162_rn(acc[mt][nt][2] * scm1 + bi0,
                                          acc[mt][nt][3] * scm1 + bi1);
            }
        }
    } else {
        __nv_bfloat16* Vout = g_v + (size_t)b * CC * SS;
#pragma unroll
        for (int mt = 0; mt < 4; mt++) {
            int m = by + wm + mt * 16 + qr;
            float bi0 = bv[m], bi1 = bv[m + 8];
#pragma unroll
            for (int nt = 0; nt < 8; nt++) {
                int n = bx + wn + nt * 8 + qc * 2;
                float scn0 = g_scale[b * SS + n];
                float scn1 = g_scale[b * SS + n + 1];
                *(__nv_bfloat162*)&Vout[(size_t)m * SS + n] =
                    __floats2bfloat162_rn(acc[mt][nt][0] * scn0 + bi0,
                                          acc[mt][nt][1] * scn1 + bi0);
                *(__nv_bfloat162*)&Vout[(size_t)(m + 8) * SS + n] =
                    __floats2bfloat162_rn(acc[mt][nt][2] * scn0 + bi1,
                                          acc[mt][nt][3] * scn1 + bi1);
            }
        }
    }
}

// ---------------------------------------------------------------------------
// QK^T (per batch, compacted grid); writes exp(scores) bf16 + partials
// ---------------------------------------------------------------------------
__global__ void __launch_bounds__(128) qk_kernel(int b) {
    int bi = blockIdx.x;
    int f = 0;
    while (bi >= 64 * (f + 1)) { bi -= 64 * (f + 1); f++; }
    int r  = bi / (8 * (f + 1));
    int nc = bi % (8 * (f + 1));
    int m0 = (f * 8 + r) * 128;   // sq
    int n0 = nc * 128;            // sk

    const __nv_bfloat16* Q = g_q + (size_t)b * SS * CC + (size_t)m0 * CC;
    const __nv_bfloat16* K = g_k + (size_t)b * SS * CC + (size_t)n0 * CC;
    GEMM_VARS
    MAINLOOP3(Q, CC, K, CC, CC / KSLAB)

    __nv_bfloat16* P = g_p + (size_t)b * SS * SS;
    int pidx = (n0 >> 6) + (wn >> 6);
#pragma unroll
    for (int mt = 0; mt < 4; mt++) {
        int m = m0 + wm + mt * 16 + qr;
        float r0 = 0.f, r1 = 0.f;
#pragma unroll
        for (int nt = 0; nt < 8; nt++) {
            int n = n0 + wn + nt * 8 + qc * 2;
            float e0 = __expf(acc[mt][nt][0] * INV_SQRT_C);
            float e1 = __expf(acc[mt][nt][1] * INV_SQRT_C);
            float e2 = __expf(acc[mt][nt][2] * INV_SQRT_C);
            float e3 = __expf(acc[mt][nt][3] * INV_SQRT_C);
            *(__nv_bfloat162*)&P[(size_t)m * SS + n]       = __floats2bfloat162_rn(e0, e1);
            *(__nv_bfloat162*)&P[(size_t)(m + 8) * SS + n] = __floats2bfloat162_rn(e2, e3);
            r0 += e0 + e1;
            r1 += e2 + e3;
        }
        r0 += __shfl_xor_sync(0xffffffffu, r0, 1);
        r0 += __shfl_xor_sync(0xffffffffu, r0, 2);
        r1 += __shfl_xor_sync(0xffffffffu, r1, 1);
        r1 += __shfl_xor_sync(0xffffffffu, r1, 2);
        if (qc == 0) {
            g_psum[((size_t)b * SS + m) * 128 + pidx]     = r0;
            g_psum[((size_t)b * SS + m + 8) * 128 + pidx] = r1;
        }
    }
}

// ---------------------------------------------------------------------------
// fold partial sums -> g_rsum (per batch)
// ---------------------------------------------------------------------------
__global__ void __launch_bounds__(128) psum_reduce_kernel(int b) {
    int sq = blockIdx.x * 4 + (threadIdx.x >> 5);
    int lane = threadIdx.x & 31;
    int cnt = ((sq / NHW) + 1) * 16;
    const float* p = g_psum + ((size_t)b * SS + sq) * 128;
    float s = 0.f;
#pragma unroll
    for (int j = 0; j < 4; j++) {
        int idx = j * 32 + lane;
        if (idx < cnt) s += p[idx];
    }
#pragma unroll
    for (int o = 16; o > 0; o >>= 1) s += __shfl_xor_sync(0xffffffffu, s, o);
    if (lane == 0) g_rsum[b * SS + sq] = s;
}

// ---------------------------------------------------------------------------
// PV (per batch): D[sq][c] = (P[sq][:L] . v[c][:L]) / rsum[sq]
// ---------------------------------------------------------------------------
__global__ void __launch_bounds__(128) pv_kernel(int b) {
    int m0 = blockIdx.y * 128;   // sq
    int n0 = blockIdx.x * 128;   // c
    int L  = (m0 / NHW + 1) * NHW;
    const int nIt = L / KSLAB;

    const __nv_bfloat16* P = g_p + (size_t)b * SS * SS + (size_t)m0 * SS;
    const __nv_bfloat16* V = g_v + (size_t)b * CC * SS + (size_t)n0 * SS;
    GEMM_VARS
    MAINLOOP3(P, SS, V, SS, nIt)

    __nv_bfloat16* O = g_o + (size_t)b * SS * CC;
#pragma unroll
    for (int mt = 0; mt < 4; mt++) {
        int m = m0 + wm + mt * 16 + qr;
        float inv0 = 1.f / g_rsum[b * SS + m];
        float inv1 = 1.f / g_rsum[b * SS + m + 8];
#pragma unroll
        for (int nt = 0; nt < 8; nt++) {
            int n = n0 + wn + nt * 8 + qc * 2;
            *(__nv_bfloat162*)&O[(size_t)m * CC + n] =
                __floats2bfloat162_rn(acc[mt][nt][0] * inv0, acc[mt][nt][1] * inv0);
            *(__nv_bfloat162*)&O[(size_t)(m + 8) * CC + n] =
                __floats2bfloat162_rn(acc[mt][nt][2] * inv1, acc[mt][nt][3] * inv1);
        }
    }
}

// ---------------------------------------------------------------------------
// O-proj + residual (per batch, fp32 out)
// ---------------------------------------------------------------------------
__global__ void __launch_bounds__(128) oproj_kernel(
    const float* __restrict__ bo, const float* __restrict__ x,
    float* __restrict__ out, int b) {

    int m0 = blockIdx.y * 128;   // c_out
    int n0 = blockIdx.x * 128;   // s

    const __nv_bfloat16* W = g_w[3] + (size_t)m0 * CC;
    const __nv_bfloat16* O = g_o + (size_t)b * SS * CC + (size_t)n0 * CC;
    GEMM_VARS
    MAINLOOP3(W, CC, O, CC, CC / KSLAB)

#pragma unroll
    for (int mt = 0; mt < 4; mt++) {
        int m = m0 + wm + mt * 16 + qr;
        float bi0 = bo[m], bi1 = bo[m + 8];
#pragma unroll
        for (int nt = 0; nt < 8; nt++) {
            int n = n0 + wn + nt * 8 + qc * 2;
            const float2 x0 = *(const float2*)&x[((size_t)b * CC + m) * SS + n];
            const float2 x1 = *(const float2*)&x[((size_t)b * CC + m + 8) * SS + n];
            float2 v0 = make_float2(acc[mt][nt][0] + bi0 + x0.x, acc[mt][nt][1] + bi0 + x0.y);
            float2 v1 = make_float2(acc[mt][nt][2] + bi1 + x1.x, acc[mt][nt][3] + bi1 + x1.y);
            *(float2*)&out[((size_t)b * CC + m) * SS + n]     = v0;
            *(float2*)&out[((size_t)b * CC + m + 8) * SS + n] = v1;
        }
    }
}

// ---------------------------------------------------------------------------
extern "C" void kernel_launch(void* const* d_in, const int* in_sizes, int n_in,
                              void* d_out, int out_size) {
    const float* x     = (const float*)d_in[0];
    const float* gamma = (const float*)d_in[1];
    const float* wq    = (const float*)d_in[2];
    const float* bq    = (const float*)d_in[3];
    const float* wk    = (const float*)d_in[4];
    const float* bk    = (const float*)d_in[5];
    const float* wv    = (const float*)d_in[6];
    const float* bv    = (const float*)d_in[7];
    const float* wo    = (const float*)d_in[8];
    const float* bo    = (const float*)d_in[9];
    float* out = (float*)d_out;

    static cudaStream_t s1 = nullptr;
    static cudaEvent_t evFork, evPrep, evDone1;
    if (!s1) {
        cudaStreamCreateWithFlags(&s1, cudaStreamNonBlocking);
        cudaEventCreateWithFlags(&evFork,  cudaEventDisableTiming);
        cudaEventCreateWithFlags(&evPrep,  cudaEventDisableTiming);
        cudaEventCreateWithFlags(&evDone1, cudaEventDisableTiming);
        cudaFuncSetAttribute(normtrans_kernel, cudaFuncAttributeMaxDynamicSharedMemorySize, SMEM_NT);
        cudaFuncSetAttribute(proj_kernel,   cudaFuncAttributeMaxDynamicSharedMemorySize, SMEM_GEMM);
        cudaFuncSetAttribute(qk_kernel,     cudaFuncAttributeMaxDynamicSharedMemorySize, SMEM_GEMM);
        cudaFuncSetAttribute(pv_kernel,     cudaFuncAttributeMaxDynamicSharedMemorySize, SMEM_GEMM);
        cudaFuncSetAttribute(oproj_kernel,  cudaFuncAttributeMaxDynamicSharedMemorySize, SMEM_GEMM);
    }

    // fork s1 from stream 0
    cudaEventRecord(evFork, 0);
    cudaStreamWaitEvent(s1, evFork, 0);

    // s1: weight prep + batch-1 chain
    prep_w_kernel<<<dim3(CC * CC / 256, 4), 256, 0, s1>>>(wq, wk, wv, wo, gamma);
    cudaEventRecord(evPrep, s1);
    normtrans_kernel<<<dim3(SS / 32, 1), 256, SMEM_NT, s1>>>(x, 1);
    proj_kernel<<<dim3(SS / 128, CC / 128, 3), 128, SMEM_GEMM, s1>>>(bq, bk, bv, 1);
    qk_kernel<<<dim3(2304, 1, 1), 128, SMEM_GEMM, s1>>>(1);
    psum_reduce_kernel<<<dim3(SS / 4, 1), 128, 0, s1>>>(1);
    pv_kernel<<<dim3(CC / 128, SS / 128, 1), 128, SMEM_GEMM, s1>>>(1);
    oproj_kernel<<<dim3(SS / 128, CC / 128, 1), 128, SMEM_GEMM, s1>>>(bo, x, out, 1);
    cudaEventRecord(evDone1, s1);

    // stream 0: batch-0 chain (proj waits on weight prep)
    normtrans_kernel<<<dim3(SS / 32, 1), 256, SMEM_NT>>>(x, 0);
    cudaStreamWaitEvent(0, evPrep, 0);
    proj_kernel<<<dim3(SS / 128, CC / 128, 3), 128, SMEM_GEMM>>>(bq, bk, bv, 0);
    qk_kernel<<<dim3(2304, 1, 1), 128, SMEM_GEMM>>>(0);
    psum_reduce_kernel<<<dim3(SS / 4, 1), 128>>>(0);
    pv_kernel<<<dim3(CC / 128, SS / 128, 1), 128, SMEM_GEMM>>>(0);
    oproj_kernel<<<dim3(SS / 128, CC / 128, 1), 128, SMEM_GEMM>>>(bo, x, out, 0);

    // join s1 back into stream 0 (required for graph capture)
    cudaStreamWaitEvent(0, evDone1, 0);
}